// round 13
// baseline (speedup 1.0000x reference)
#include <cuda_runtime.h>
#include <cuda_fp16.h>
#include <math.h>
#include <stdint.h>

// Problem constants
#define BB 2
#define QQ 4096
#define CC 64
#define HH 64
#define WW 64
#define CK 576          // C*9
#define KIN 580         // CK + 4
#define KINP 608        // K padding for layer-1 (mult of 32)
#define CKP 640         // N padding for layer-2 (mult of 128)
#define HID 256
#define NROW (BB*QQ)        // 8192
#define NROW4 (BB*QQ*4)     // 32768

// ---------------- scratch (device globals; no allocation) ----------------
__device__ __half g_INPh[NROW4 * KINP + 64];  // [32768, 608] (+64 pad: unguarded epi-mul read)
__device__ float  g_QRYp[NROW * CKP];         // [8192, 640] fp32, cols 576.. zero
__device__ __half g_Hh  [NROW4 * 512];        // cols 0..255 Hk, 256..511 Hv
__device__ __half g_PVh [NROW4 * CKP];        // stride 640
__device__ float  g_attn[NROW4];              // fused dot accumulators
__device__ float  g_W   [NROW4];              // softmax weights (4 per bq)
__device__ __half g_Xh  [NROW * CK];
__device__ __half g_Hqh [NROW * HID];
// weights, [N, K] K-major, fp16
__device__ __half g_W1t [512 * KINP];         // kW1t rows 0..255, vW1t rows 256..511
__device__ float  g_b1  [512];
__device__ __half g_kW2t[CKP * HID];          // rows 576..639 zero
__device__ __half g_vW2t[CKP * HID];
__device__ float  g_kb2p[CKP];                // padded biases
__device__ float  g_vb2p[CKP];
__device__ __half g_qW1t[HID * CK];

__device__ __forceinline__ uint32_t s2u(const void* p) {
    uint32_t a;
    asm("{ .reg .u64 t; cvta.to.shared.u64 t, %1; cvt.u32.u64 %0, t; }" : "=r"(a) : "l"(p));
    return a;
}

// ---------------- weight transpose / pad / fp16 ----------------------------
__global__ void prep_weights(const float* __restrict__ kW1, const float* __restrict__ vW1,
                             const float* __restrict__ kW2, const float* __restrict__ vW2,
                             const float* __restrict__ qW1,
                             const float* __restrict__ kb1, const float* __restrict__ vb1,
                             const float* __restrict__ kb2, const float* __restrict__ vb2) {
    int i = blockIdx.x * 256 + threadIdx.x;
    if (i < 512 * KINP) {           // fused W1: [512, 608]
        int n = i / KINP, k = i - n * KINP;
        float v = 0.f;
        if (k < KIN) v = (n < HID) ? kW1[k * HID + n] : vW1[k * HID + (n - HID)];
        g_W1t[i] = __float2half_rn(v);
    }
    if (i < CKP * HID) {            // [640, 256] from [256, 576], zero rows >= 576
        int n = i / HID, k = i - n * HID;
        float a = 0.f, b = 0.f;
        if (n < CK) { a = kW2[k * CK + n]; b = vW2[k * CK + n]; }
        g_kW2t[i] = __float2half_rn(a);
        g_vW2t[i] = __float2half_rn(b);
    }
    if (i < HID * CK) {             // [256, 576] from [576, 256]
        int n = i / CK, k = i - n * CK;
        g_qW1t[i] = __float2half_rn(qW1[k * HID + n]);
    }
    if (i < 512)
        g_b1[i] = (i < HID) ? kb1[i] : vb1[i - HID];
    if (i < CKP) {
        g_kb2p[i] = (i < CK) ? kb2[i] : 0.f;
        g_vb2p[i] = (i < CK) ? vb2[i] : 0.f;
    }
}

// ---------------- setup: gather unfold samples, build INP + query ----------
__device__ __forceinline__ int nearest_idx(float c) {
    float f = ((c + 1.0f) * 64.0f - 1.0f) * 0.5f + 0.5f;
    int i = (int)floorf(f);
    return i < 0 ? 0 : (i > 63 ? 63 : i);
}

__global__ __launch_bounds__(128) void setup_kernel(
    const float* __restrict__ feature, const float* __restrict__ coord,
    const float* __restrict__ scale) {
    const int bq = blockIdx.x;
    const int b  = bq >> 12;
    const int tid = threadIdx.x;

    const float cy = coord[bq * 2 + 0];
    const float cx = coord[bq * 2 + 1];
    const float s0 = scale[bq * 2 + 0];
    const float s1 = scale[bq * 2 + 1];
    const float lo = -1.0f + 1e-6f, hi = 1.0f - 1e-6f;

    int   qy[4], qx[4];
    float area[4];
    const float rx = 1.0f / 64.0f, ry = 1.0f / 64.0f;
    #pragma unroll
    for (int s = 0; s < 4; s++) {
        float vx = (s >= 2) ? 1.0f : -1.0f;
        float vy = (s & 1)  ? 1.0f : -1.0f;
        float c0 = fminf(fmaxf(cy + vx * rx + 1e-6f, lo), hi);
        float c1 = fminf(fmaxf(cx + vy * ry + 1e-6f, lo), hi);
        int iy = nearest_idx(c0), ix = nearest_idx(c1);
        qy[s] = iy; qx[s] = ix;
        float qc0 = -1.0f + (2.0f * iy + 1.0f) / 64.0f;
        float qc1 = -1.0f + (2.0f * ix + 1.0f) / 64.0f;
        area[s] = fabsf((cy - qc0) * 64.0f * (cx - qc1) * 64.0f) + 1e-9f;
    }
    float tot = area[0] + area[1] + area[2] + area[3];
    float qw[4];
    #pragma unroll
    for (int s = 0; s < 4; s++) qw[s] = area[3 - s] / tot;

    const float sc00 = scale[(b * QQ) * 2 + 0];
    const float sc01 = scale[(b * QQ) * 2 + 1];
    const float invtx = (1.0f - sc00) / 63.0f;
    const float invty = (1.0f - sc01) / 63.0f;
    int   ky[4], kx[4];
    float kr0[4], kr1[4];
    #pragma unroll
    for (int s = 0; s < 4; s++) {
        float vx = (s >= 2) ? 1.0f : -1.0f;
        float vy = (s & 1)  ? 1.0f : -1.0f;
        float c0 = fminf(fmaxf(cy + vx * invtx + 1e-6f, lo), hi);
        float c1 = fminf(fmaxf(cx + vy * invty + 1e-6f, lo), hi);
        int iy = nearest_idx(c0), ix = nearest_idx(c1);
        ky[s] = iy; kx[s] = ix;
        float qc0 = -1.0f + (2.0f * iy + 1.0f) / 64.0f;
        float qc1 = -1.0f + (2.0f * ix + 1.0f) / 64.0f;
        kr0[s] = (cy - qc0) * 64.0f;
        kr1[s] = (cx - qc1) * 64.0f;
    }

    const float* fb = feature + (size_t)b * CC * HH * WW;
    for (int k = tid; k < CK; k += 128) {
        int c = k / 9, p = k - c * 9;
        int di = p / 3 - 1, dj = p - (p / 3) * 3 - 1;
        const float* fc = fb + (size_t)c * (HH * WW);
        float qacc = 0.f;
        #pragma unroll
        for (int s = 0; s < 4; s++) {
            int y = qy[s] + di, x = qx[s] + dj;
            float v = ((unsigned)y < 64u && (unsigned)x < 64u) ? fc[y * 64 + x] : 0.f;
            qacc += qw[s] * v;
        }
        g_QRYp[(size_t)bq * CKP + k] = qacc;
        #pragma unroll
        for (int s = 0; s < 4; s++) {
            int y = ky[s] + di, x = kx[s] + dj;
            float v = ((unsigned)y < 64u && (unsigned)x < 64u) ? fc[y * 64 + x] : 0.f;
            g_INPh[((size_t)(bq * 4 + s)) * KINP + k] = __float2half_rn(v);
        }
    }
    if (tid < 64)        // zero query pad cols 576..639
        g_QRYp[(size_t)bq * CKP + CK + tid] = 0.f;
    if (tid < 4)         // zero attn accumulators (re-zeroed every launch)
        g_attn[bq * 4 + tid] = 0.f;
    {   // cols 576..607: rel(2), scale(2), zeros. 128 thr = 4 shifts x 32 cols.
        int s = tid >> 5, cc = tid & 31;
        float v = 0.f;
        if (cc == 0) v = kr0[s];
        else if (cc == 1) v = kr1[s];
        else if (cc == 2) v = s0 * 64.0f;
        else if (cc == 3) v = s1 * 64.0f;
        g_INPh[((size_t)(bq * 4 + s)) * KINP + 576 + cc] = __float2half_rn(v);
    }
}

// ---------------- fp16 mma.sync GEMM (BM=256, warp tile 64x64) --------------
// C[M,N] = A[M,K(lda)] @ B[N,K]^T, half in, fp32 acc.  K = 32*S (template).
// BM=256, BN=128, BK=32, 8 warps (4x2), warp tile 64x64, 3-stage cp.async,
// stage loop fully unrolled.  REQUIRES M%256==0, N%128==0, K%32==0.
// blockIdx.z picks operand set 0/1.
// EPI 0: half(relu(acc+bias)) -> C.
// EPI 2: z=0 (k): dot((acc+bias)*mul, query) -> atomicAdd g_attn, no store.
//        z=1 (v): half((acc+bias)*mul) -> C.
#define ATILEB 16384                // 256 rows x 64 B
#define BTILEB 8192                 // 128 rows x 64 B
#define STAGEB (ATILEB + BTILEB)    // 24576
#define SMEMB (3*STAGEB)            // 73728

__device__ __forceinline__ void cp16(uint32_t dst, const __half* src) {
    asm volatile("cp.async.cg.shared.global [%0], [%1], 16;" :: "r"(dst), "l"(src) : "memory");
}
#define MMA_F16(acc, a0, a1, a2, a3, b0, b1)                                     \
    asm volatile("mma.sync.aligned.m16n8k16.row.col.f32.f16.f16.f32 "            \
        "{%0,%1,%2,%3}, {%4,%5,%6,%7}, {%8,%9}, {%0,%1,%2,%3};"                  \
        : "+f"((acc)[0]), "+f"((acc)[1]), "+f"((acc)[2]), "+f"((acc)[3])         \
        : "r"(a0), "r"(a1), "r"(a2), "r"(a3), "r"(b0), "r"(b1))

template<int EPI, int S>
__global__ __launch_bounds__(256) void mma_gemm(
    const __half* __restrict__ A0, const __half* __restrict__ A1, int lda,
    const __half* __restrict__ B0, const __half* __restrict__ B1,
    __half* __restrict__ C0, __half* __restrict__ C1,
    const float* __restrict__ bias0, const float* __restrict__ bias1,
    const __half* __restrict__ mul, int ldmul, int N) {
    extern __shared__ char smem[];
    constexpr int K = 32 * S;
    const int tid = threadIdx.x;
    const int lane = tid & 31, wid = tid >> 5;
    const int g = lane >> 2, tg = lane & 3;
    const int wm = (wid & 3) * 64, wn = (wid >> 2) * 64;
    const int bm = blockIdx.y * 256, bn = blockIdx.x * 128;
    const uint32_t sbase = s2u(smem);

    const __half* A = blockIdx.z ? A1 : A0;
    const __half* B = blockIdx.z ? B1 : B0;
    __half*       C = blockIdx.z ? C1 : C0;
    const float* bias = blockIdx.z ? bias1 : bias0;

    // per-thread fixed load coordinates (hoisted once)
    const int ldrow = tid >> 2, ldq = tid & 3;             // base rows 0..63
    const __half* gA = A + (size_t)(bm + ldrow) * lda + ldq * 8;
    const __half* gB = B + (size_t)(bn + ldrow) * K + ldq * 8;
    const size_t a64 = (size_t)64 * lda;                    // A row-chunk stride
    const uint32_t sAo = (uint32_t)(ldrow * 64 + ldq * 16);
    const uint32_t sBo = sAo + ATILEB;

    float acc[4][8][4];
    #pragma unroll
    for (int mt = 0; mt < 4; mt++)
        #pragma unroll
        for (int nt = 0; nt < 8; nt++)
            #pragma unroll
            for (int j = 0; j < 4; j++) acc[mt][nt][j] = 0.f;

    // smem fragment offsets (halves), hoisted
    const uint32_t fa0 = (uint32_t)((wm + g) * 32 + 8 * tg);
    const uint32_t fb0 = (uint32_t)((wn + g) * 32 + 8 * tg);

    #pragma unroll
    for (int p = 0; p < 2; p++) {          // prologue stages 0,1
        uint32_t st = sbase + p * STAGEB;
        cp16(st + sAo,              gA + p * 32);
        cp16(st + sAo + 64 * 64,    gA + a64 + p * 32);
        cp16(st + sAo + 128 * 64,   gA + 2 * a64 + p * 32);
        cp16(st + sAo + 192 * 64,   gA + 3 * a64 + p * 32);
        cp16(st + sBo,              gB + p * 32);
        cp16(st + sBo + 64 * 64,    gB + (size_t)64 * K + p * 32);
        asm volatile("cp.async.commit_group;" ::: "memory");
    }

    #pragma unroll
    for (int s = 0; s < S; s++) {
        asm volatile("cp.async.wait_group 1;" ::: "memory");
        __syncthreads();

        if (s + 2 < S) {
            uint32_t st = sbase + ((s + 2) % 3) * STAGEB;   // compile-time folded
            cp16(st + sAo,              gA + (s + 2) * 32);
            cp16(st + sAo + 64 * 64,    gA + a64 + (s + 2) * 32);
            cp16(st + sAo + 128 * 64,   gA + 2 * a64 + (s + 2) * 32);
            cp16(st + sAo + 192 * 64,   gA + 3 * a64 + (s + 2) * 32);
            cp16(st + sBo,              gB + (s + 2) * 32);
            cp16(st + sBo + 64 * 64,    gB + (size_t)64 * K + (s + 2) * 32);
            asm volatile("cp.async.commit_group;" ::: "memory");
        }

        const __half* As = (const __half*)(smem + (s % 3) * STAGEB);
        const __half* Bs = As + ATILEB / 2;

        uint4 a0[4], a1[4];
        #pragma unroll
        for (int mt = 0; mt < 4; mt++) {
            a0[mt] = *(const uint4*)(As + fa0 + mt * 16 * 32);
            a1[mt] = *(const uint4*)(As + fa0 + mt * 16 * 32 + 8 * 32);
        }
        #pragma unroll
        for (int nt = 0; nt < 8; nt++) {
            uint4 bv = *(const uint4*)(Bs + fb0 + nt * 8 * 32);
            #pragma unroll
            for (int mt = 0; mt < 4; mt++) {
                MMA_F16(acc[mt][nt], a0[mt].x, a1[mt].x, a0[mt].y, a1[mt].y, bv.x, bv.y);
                MMA_F16(acc[mt][nt], a0[mt].z, a1[mt].z, a0[mt].w, a1[mt].w, bv.z, bv.w);
            }
        }
        __syncthreads();
    }

    // epilogue: c0,c1 -> row g cols 2tg,2tg+1; c2,c3 -> row g+8
    if (EPI == 0 || blockIdx.z == 1) {
        #pragma unroll
        for (int mt = 0; mt < 4; mt++) {
            int gm0 = bm + wm + mt * 16 + g;
            #pragma unroll
            for (int nt = 0; nt < 8; nt++) {
                int gn = bn + wn + nt * 8 + 2 * tg;
                float b0 = bias[gn], b1 = bias[gn + 1];
                float v0 = acc[mt][nt][0] + b0;
                float v1 = acc[mt][nt][1] + b1;
                float v2 = acc[mt][nt][2] + b0;
                float v3 = acc[mt][nt][3] + b1;
                if (EPI == 0) {
                    v0 = fmaxf(v0, 0.f); v1 = fmaxf(v1, 0.f);
                    v2 = fmaxf(v2, 0.f); v3 = fmaxf(v3, 0.f);
                } else {
                    float2 m0v = __half22float2(*(const __half2*)(mul + (size_t)gm0 * ldmul + gn));
                    float2 m1v = __half22float2(*(const __half2*)(mul + (size_t)(gm0 + 8) * ldmul + gn));
                    v0 *= m0v.x; v1 *= m0v.y; v2 *= m1v.x; v3 *= m1v.y;
                }
                *(__half2*)(C + (size_t)gm0 * N + gn) = __floats2half2_rn(v0, v1);
                *(__half2*)(C + (size_t)(gm0 + 8) * N + gn) = __floats2half2_rn(v2, v3);
            }
        }
    } else {
        // EPI==2, z==0 (k-side): fused attention dot, no store
        #pragma unroll
        for (int mt = 0; mt < 4; mt++) {
            int gm0 = bm + wm + mt * 16 + g;
            const float* q0 = g_QRYp + (size_t)(gm0 >> 2) * CKP;
            const float* q1 = g_QRYp + (size_t)((gm0 + 8) >> 2) * CKP;
            float dot0 = 0.f, dot1 = 0.f;
            #pragma unroll
            for (int nt = 0; nt < 8; nt++) {
                int gn = bn + wn + nt * 8 + 2 * tg;
                float b0 = bias[gn], b1 = bias[gn + 1];
                float2 m0v = __half22float2(*(const __half2*)(mul + (size_t)gm0 * ldmul + gn));
                float2 m1v = __half22float2(*(const __half2*)(mul + (size_t)(gm0 + 8) * ldmul + gn));
                float v0 = (acc[mt][nt][0] + b0) * m0v.x;
                float v1 = (acc[mt][nt][1] + b1) * m0v.y;
                float v2 = (acc[mt][nt][2] + b0) * m1v.x;
                float v3 = (acc[mt][nt][3] + b1) * m1v.y;
                float2 qa = *(const float2*)(q0 + gn);
                float2 qb = *(const float2*)(q1 + gn);
                dot0 += v0 * qa.x + v1 * qa.y;
                dot1 += v2 * qb.x + v3 * qb.y;
            }
            dot0 += __shfl_xor_sync(0xffffffffu, dot0, 1);
            dot0 += __shfl_xor_sync(0xffffffffu, dot0, 2);
            dot1 += __shfl_xor_sync(0xffffffffu, dot1, 1);
            dot1 += __shfl_xor_sync(0xffffffffu, dot1, 2);
            if (tg == 0) {
                atomicAdd(&g_attn[gm0], dot0);
                atomicAdd(&g_attn[gm0 + 8], dot1);
            }
        }
    }
}

// ---------------- softmax over the 4 shifts --------------------------------
__global__ __launch_bounds__(256) void softmax_kernel() {
    int bq = blockIdx.x * 256 + threadIdx.x;     // 8192 threads
    float4 a = *(const float4*)&g_attn[bq * 4];
    float m = fmaxf(fmaxf(a.x, a.y), fmaxf(a.z, a.w));
    float e0 = expf(a.x - m), e1 = expf(a.y - m), e2 = expf(a.z - m), e3 = expf(a.w - m);
    float inv = 1.0f / (e0 + e1 + e2 + e3);
    float4 w = {e0 * inv, e1 * inv, e2 * inv, e3 * inv};
    *(float4*)&g_W[bq * 4] = w;
}

// ---------------- weighted PV sum -> X -------------------------------------
__global__ __launch_bounds__(160) void attnw_kernel() {
    const int bq = blockIdx.x;
    const int tid = threadIdx.x;
    if (tid < 144) {                       // CK/4 = 144, 4 halves per thread
        float4 w = *(const float4*)&g_W[bq * 4];
        const __half* pv = g_PVh + (size_t)bq * 4 * CKP;
        float x0 = 0.f, x1 = 0.f, x2 = 0.f, x3 = 0.f;
        float ws[4] = {w.x, w.y, w.z, w.w};
        #pragma unroll
        for (int s = 0; s < 4; s++) {
            uint2 u = *(const uint2*)(pv + (size_t)s * CKP + tid * 4);
            float2 f0 = __half22float2(*(__half2*)&u.x);
            float2 f1 = __half22float2(*(__half2*)&u.y);
            x0 += ws[s] * f0.x; x1 += ws[s] * f0.y;
            x2 += ws[s] * f1.x; x3 += ws[s] * f1.y;
        }
        __half2* xp = (__half2*)(g_Xh + (size_t)bq * CK);
        xp[tid * 2 + 0] = __floats2half2_rn(x0, x1);
        xp[tid * 2 + 1] = __floats2half2_rn(x2, x3);
    }
}

// ---------------- final projection: [8192,256] @ [256,3] + bias ------------
__global__ __launch_bounds__(128) void outproj_kernel(
    const float* __restrict__ qW2, const float* __restrict__ qb2,
    float* __restrict__ out) {
    int warp = threadIdx.x >> 5, lane = threadIdx.x & 31;
    int row = blockIdx.x * 4 + warp;
    const __half* h = g_Hqh + (size_t)row * HID;
    float a0 = 0.f, a1 = 0.f, a2 = 0.f;
    #pragma unroll
    for (int i = 0; i < 8; i++) {
        int k = i * 32 + lane;
        float a = __half2float(h[k]);
        a0 += a * qW2[k * 3 + 0];
        a1 += a * qW2[k * 3 + 1];
        a2 += a * qW2[k * 3 + 2];
    }
    #pragma unroll
    for (int off = 16; off; off >>= 1) {
        a0 += __shfl_down_sync(0xffffffffu, a0, off);
        a1 += __shfl_down_sync(0xffffffffu, a1, off);
        a2 += __shfl_down_sync(0xffffffffu, a2, off);
    }
    if (lane == 0) {
        out[row * 3 + 0] = a0 + qb2[0];
        out[row * 3 + 1] = a1 + qb2[1];
        out[row * 3 + 2] = a2 + qb2[2];
    }
}

// ---------------- launch ---------------------------------------------------
extern "C" void kernel_launch(void* const* d_in, const int* in_sizes, int n_in,
                              void* d_out, int out_size) {
    const float* feature = (const float*)d_in[0];
    const float* coord   = (const float*)d_in[1];
    const float* scale   = (const float*)d_in[2];
    const float* kW1 = (const float*)d_in[3];
    const float* kb1 = (const float*)d_in[4];
    const float* kW2 = (const float*)d_in[5];
    const float* kb2 = (const float*)d_in[6];
    const float* vW1 = (const float*)d_in[7];
    const float* vb1 = (const float*)d_in[8];
    const float* vW2 = (const float*)d_in[9];
    const float* vb2 = (const float*)d_in[10];
    const float* qW1 = (const float*)d_in[11];
    const float* qb1 = (const float*)d_in[12];
    const float* qW2 = (const float*)d_in[13];
    const float* qb2 = (const float*)d_in[14];
    float* out = (float*)d_out;

    __half *pINP, *pH, *pPV, *pX, *pHq, *pW1t, *pkW2t, *pvW2t, *pqW1t;
    float *pb1, *pkb2p, *pvb2p;
    cudaGetSymbolAddress((void**)&pINP,  g_INPh);
    cudaGetSymbolAddress((void**)&pH,    g_Hh);
    cudaGetSymbolAddress((void**)&pPV,   g_PVh);
    cudaGetSymbolAddress((void**)&pX,    g_Xh);
    cudaGetSymbolAddress((void**)&pHq,   g_Hqh);
    cudaGetSymbolAddress((void**)&pW1t,  g_W1t);
    cudaGetSymbolAddress((void**)&pb1,   g_b1);
    cudaGetSymbolAddress((void**)&pkW2t, g_kW2t);
    cudaGetSymbolAddress((void**)&pvW2t, g_vW2t);
    cudaGetSymbolAddress((void**)&pkb2p, g_kb2p);
    cudaGetSymbolAddress((void**)&pvb2p, g_vb2p);
    cudaGetSymbolAddress((void**)&pqW1t, g_qW1t);

    cudaFuncSetAttribute(mma_gemm<0, 19>, cudaFuncAttributeMaxDynamicSharedMemorySize, SMEMB);
    cudaFuncSetAttribute(mma_gemm<2, 8>,  cudaFuncAttributeMaxDynamicSharedMemorySize, SMEMB);
    cudaFuncSetAttribute(mma_gemm<0, 18>, cudaFuncAttributeMaxDynamicSharedMemorySize, SMEMB);

    // 0) transpose/pad weights -> fp16
    prep_weights<<<(512 * KINP + 255) / 256, 256>>>(kW1, vW1, kW2, vW2, qW1,
                                                    kb1, vb1, kb2, vb2);

    // 1) gather/setup (also zeros g_attn + query pad)
    setup_kernel<<<NROW, 128>>>(feature, coord, scale);

    // 2) fused layer-1:  H[:, 0:512] = relu(INP @ W1t^T + b1), K=608, N=512
    {
        dim3 grid(4, NROW4 / 256, 1);
        mma_gemm<0, 19><<<grid, 256, SMEMB>>>(pINP, pINP, KINP, pW1t, pW1t, pH, pH,
                                              pb1, pb1, nullptr, 0, 512);
    }

    // 3) layer-2 merged: z=0 k-side (fused dot -> g_attn, no store),
    //                    z=1 v-side (PV store). K=256, N=640.
    {
        dim3 grid(CKP / 128, NROW4 / 256, 2);
        mma_gemm<2, 8><<<grid, 256, SMEMB>>>(pH, pH + 256, 512, pkW2t, pvW2t,
                                             pPV, pPV, pkb2p, pvb2p,
                                             pINP, KINP, CKP);
    }

    // 4) softmax over shifts, then weighted PV sum -> X
    softmax_kernel<<<NROW / 256, 256>>>();
    attnw_kernel<<<NROW, 160>>>();

    // 5) query MLP layer 1: Hq = relu(X @ qW1t^T + qb1), K=576, N=256
    {
        dim3 grid(2, NROW / 256, 1);
        mma_gemm<0, 18><<<grid, 256, SMEMB>>>(pX, pX, CK, pqW1t, pqW1t, pHq, pHq,
                                              qb1, qb1, nullptr, 0, 256);
    }

    // 6) output projection  [8192 x 3]
    outproj_kernel<<<NROW / 4, 128>>>(qW2, qb2, out);
}

// round 15
// speedup vs baseline: 1.2734x; 1.2734x over previous
#include <cuda_runtime.h>
#include <cuda_fp16.h>
#include <math.h>
#include <stdint.h>

// Problem constants
#define BB 2
#define QQ 4096
#define CC 64
#define HH 64
#define WW 64
#define CK 576          // C*9
#define KIN 580         // CK + 4
#define KINP 608        // K padding for layer-1 (mult of 32)
#define CKP 640         // N padding for layer-2 (mult of 128)
#define HID 256
#define NROW (BB*QQ)        // 8192
#define NROW4 (BB*QQ*4)     // 32768

// ---------------- scratch (device globals; no allocation) ----------------
__device__ __half g_INPh[NROW4 * KINP + 64];  // [32768, 608] (+64 pad: unguarded epi-mul read)
__device__ float  g_QRYp[NROW * CKP];         // [8192, 640] fp32, cols 576.. zero
__device__ __half g_Hh  [NROW4 * 512];        // cols 0..255 Hk, 256..511 Hv
__device__ __half g_PVh [NROW4 * CKP];        // stride 640
__device__ float  g_attn[NROW4];              // fused dot accumulators
__device__ float  g_W   [NROW4];              // softmax weights (4 per bq)
__device__ __half g_Xh  [NROW * CK];
__device__ __half g_Hqh [NROW * HID];
// weights, [N, K] K-major, fp16
__device__ __half g_W1t [512 * KINP];         // kW1t rows 0..255, vW1t rows 256..511
__device__ float  g_b1  [512];
__device__ __half g_kW2t[CKP * HID];          // rows 576..639 zero
__device__ __half g_vW2t[CKP * HID];
__device__ float  g_kb2p[CKP];                // padded biases
__device__ float  g_vb2p[CKP];
__device__ __half g_qW1t[HID * CK];

__device__ __forceinline__ uint32_t s2u(const void* p) {
    uint32_t a;
    asm("{ .reg .u64 t; cvta.to.shared.u64 t, %1; cvt.u32.u64 %0, t; }" : "=r"(a) : "l"(p));
    return a;
}

// ---------------- weight transpose / pad / fp16 ----------------------------
__global__ void prep_weights(const float* __restrict__ kW1, const float* __restrict__ vW1,
                             const float* __restrict__ kW2, const float* __restrict__ vW2,
                             const float* __restrict__ qW1,
                             const float* __restrict__ kb1, const float* __restrict__ vb1,
                             const float* __restrict__ kb2, const float* __restrict__ vb2) {
    int i = blockIdx.x * 256 + threadIdx.x;
    if (i < 512 * KINP) {           // fused W1: [512, 608]
        int n = i / KINP, k = i - n * KINP;
        float v = 0.f;
        if (k < KIN) v = (n < HID) ? kW1[k * HID + n] : vW1[k * HID + (n - HID)];
        g_W1t[i] = __float2half_rn(v);
    }
    if (i < CKP * HID) {            // [640, 256] from [256, 576], zero rows >= 576
        int n = i / HID, k = i - n * HID;
        float a = 0.f, b = 0.f;
        if (n < CK) { a = kW2[k * CK + n]; b = vW2[k * CK + n]; }
        g_kW2t[i] = __float2half_rn(a);
        g_vW2t[i] = __float2half_rn(b);
    }
    if (i < HID * CK) {             // [256, 576] from [576, 256]
        int n = i / CK, k = i - n * CK;
        g_qW1t[i] = __float2half_rn(qW1[k * HID + n]);
    }
    if (i < 512)
        g_b1[i] = (i < HID) ? kb1[i] : vb1[i - HID];
    if (i < CKP) {
        g_kb2p[i] = (i < CK) ? kb2[i] : 0.f;
        g_vb2p[i] = (i < CK) ? vb2[i] : 0.f;
    }
}

// ---------------- setup: gather unfold samples, build INP + query ----------
__device__ __forceinline__ int nearest_idx(float c) {
    float f = ((c + 1.0f) * 64.0f - 1.0f) * 0.5f + 0.5f;
    int i = (int)floorf(f);
    return i < 0 ? 0 : (i > 63 ? 63 : i);
}

__global__ __launch_bounds__(128) void setup_kernel(
    const float* __restrict__ feature, const float* __restrict__ coord,
    const float* __restrict__ scale) {
    const int bq = blockIdx.x;
    const int b  = bq >> 12;
    const int tid = threadIdx.x;

    const float cy = coord[bq * 2 + 0];
    const float cx = coord[bq * 2 + 1];
    const float s0 = scale[bq * 2 + 0];
    const float s1 = scale[bq * 2 + 1];
    const float lo = -1.0f + 1e-6f, hi = 1.0f - 1e-6f;

    int   qy[4], qx[4];
    float area[4];
    const float rx = 1.0f / 64.0f, ry = 1.0f / 64.0f;
    #pragma unroll
    for (int s = 0; s < 4; s++) {
        float vx = (s >= 2) ? 1.0f : -1.0f;
        float vy = (s & 1)  ? 1.0f : -1.0f;
        float c0 = fminf(fmaxf(cy + vx * rx + 1e-6f, lo), hi);
        float c1 = fminf(fmaxf(cx + vy * ry + 1e-6f, lo), hi);
        int iy = nearest_idx(c0), ix = nearest_idx(c1);
        qy[s] = iy; qx[s] = ix;
        float qc0 = -1.0f + (2.0f * iy + 1.0f) / 64.0f;
        float qc1 = -1.0f + (2.0f * ix + 1.0f) / 64.0f;
        area[s] = fabsf((cy - qc0) * 64.0f * (cx - qc1) * 64.0f) + 1e-9f;
    }
    float tot = area[0] + area[1] + area[2] + area[3];
    float qw[4];
    #pragma unroll
    for (int s = 0; s < 4; s++) qw[s] = area[3 - s] / tot;

    const float sc00 = scale[(b * QQ) * 2 + 0];
    const float sc01 = scale[(b * QQ) * 2 + 1];
    const float invtx = (1.0f - sc00) / 63.0f;
    const float invty = (1.0f - sc01) / 63.0f;
    int   ky[4], kx[4];
    float kr0[4], kr1[4];
    #pragma unroll
    for (int s = 0; s < 4; s++) {
        float vx = (s >= 2) ? 1.0f : -1.0f;
        float vy = (s & 1)  ? 1.0f : -1.0f;
        float c0 = fminf(fmaxf(cy + vx * invtx + 1e-6f, lo), hi);
        float c1 = fminf(fmaxf(cx + vy * invty + 1e-6f, lo), hi);
        int iy = nearest_idx(c0), ix = nearest_idx(c1);
        ky[s] = iy; kx[s] = ix;
        float qc0 = -1.0f + (2.0f * iy + 1.0f) / 64.0f;
        float qc1 = -1.0f + (2.0f * ix + 1.0f) / 64.0f;
        kr0[s] = (cy - qc0) * 64.0f;
        kr1[s] = (cx - qc1) * 64.0f;
    }

    const float* fb = feature + (size_t)b * CC * HH * WW;
    for (int k = tid; k < CK; k += 128) {
        int c = k / 9, p = k - c * 9;
        int di = p / 3 - 1, dj = p - (p / 3) * 3 - 1;
        const float* fc = fb + (size_t)c * (HH * WW);
        float qacc = 0.f;
        #pragma unroll
        for (int s = 0; s < 4; s++) {
            int y = qy[s] + di, x = qx[s] + dj;
            float v = ((unsigned)y < 64u && (unsigned)x < 64u) ? fc[y * 64 + x] : 0.f;
            qacc += qw[s] * v;
        }
        g_QRYp[(size_t)bq * CKP + k] = qacc;
        #pragma unroll
        for (int s = 0; s < 4; s++) {
            int y = ky[s] + di, x = kx[s] + dj;
            float v = ((unsigned)y < 64u && (unsigned)x < 64u) ? fc[y * 64 + x] : 0.f;
            g_INPh[((size_t)(bq * 4 + s)) * KINP + k] = __float2half_rn(v);
        }
    }
    if (tid < 64)        // zero query pad cols 576..639
        g_QRYp[(size_t)bq * CKP + CK + tid] = 0.f;
    if (tid < 4)         // zero attn accumulators (re-zeroed every launch)
        g_attn[bq * 4 + tid] = 0.f;
    {   // cols 576..607: rel(2), scale(2), zeros. 128 thr = 4 shifts x 32 cols.
        int s = tid >> 5, cc = tid & 31;
        float v = 0.f;
        if (cc == 0) v = kr0[s];
        else if (cc == 1) v = kr1[s];
        else if (cc == 2) v = s0 * 64.0f;
        else if (cc == 3) v = s1 * 64.0f;
        g_INPh[((size_t)(bq * 4 + s)) * KINP + 576 + cc] = __float2half_rn(v);
    }
}

// ---------------- fp16 mma.sync GEMM (compile-time K, 4-stage) --------------
// C[M,N] = A[M,K(lda)] @ B[N,K]^T, half in, fp32 acc.  K = 32*S (template).
// BM=128, BN=128, BK=32, warp tile 32x64 (4x2 warps), 4-stage cp.async,
// stage loop fully unrolled.  REQUIRES M%128==0, N%128==0, K%32==0.
// blockIdx.z picks operand set 0/1.
// EPI 0: half(relu(acc+bias)) -> C.
// EPI 2: z=0 (k): dot((acc+bias)*mul, query) -> atomicAdd g_attn, no store.
//        z=1 (v): half((acc+bias)*mul) -> C.
#define TILEB 8192                  // bytes per operand tile
#define STAGEB 16384
#define NSTG 4
#define SMEMB (NSTG*STAGEB)         // 65536

__device__ __forceinline__ void cp16(uint32_t dst, const __half* src) {
    asm volatile("cp.async.cg.shared.global [%0], [%1], 16;" :: "r"(dst), "l"(src) : "memory");
}
#define MMA_F16(acc, a0, a1, a2, a3, b0, b1)                                     \
    asm volatile("mma.sync.aligned.m16n8k16.row.col.f32.f16.f16.f32 "            \
        "{%0,%1,%2,%3}, {%4,%5,%6,%7}, {%8,%9}, {%0,%1,%2,%3};"                  \
        : "+f"((acc)[0]), "+f"((acc)[1]), "+f"((acc)[2]), "+f"((acc)[3])         \
        : "r"(a0), "r"(a1), "r"(a2), "r"(a3), "r"(b0), "r"(b1))

template<int EPI, int S>
__global__ __launch_bounds__(256, 2) void mma_gemm(
    const __half* __restrict__ A0, const __half* __restrict__ A1, int lda,
    const __half* __restrict__ B0, const __half* __restrict__ B1,
    __half* __restrict__ C0, __half* __restrict__ C1,
    const float* __restrict__ bias0, const float* __restrict__ bias1,
    const __half* __restrict__ mul, int ldmul, int N) {
    extern __shared__ char smem[];
    constexpr int K = 32 * S;
    const int tid = threadIdx.x;
    const int lane = tid & 31, wid = tid >> 5;
    const int g = lane >> 2, tg = lane & 3;
    const int wm = (wid & 3) * 32, wn = (wid >> 2) * 64;
    const int bm = blockIdx.y * 128, bn = blockIdx.x * 128;
    const uint32_t sbase = s2u(smem);

    const __half* A = blockIdx.z ? A1 : A0;
    const __half* B = blockIdx.z ? B1 : B0;
    __half*       C = blockIdx.z ? C1 : C0;
    const float* bias = blockIdx.z ? bias1 : bias0;

    // per-thread fixed load coordinates (hoisted once)
    const int ldrow = tid >> 2, ldq = tid & 3;             // rows 0..63 (+64 second chunk)
    const __half* gA0 = A + (size_t)(bm + ldrow) * lda + ldq * 8;
    const __half* gA1 = A + (size_t)(bm + ldrow + 64) * lda + ldq * 8;
    const __half* gB0 = B + (size_t)(bn + ldrow) * K + ldq * 8;
    const __half* gB1 = B + (size_t)(bn + ldrow + 64) * K + ldq * 8;
    const uint32_t sAo = (uint32_t)(ldrow * 64 + ldq * 16);
    const uint32_t sBo = sAo + TILEB;
    const uint32_t sA1o = sAo + 64 * 64;
    const uint32_t sB1o = sBo + 64 * 64;

    float acc[2][8][4];
    #pragma unroll
    for (int mt = 0; mt < 2; mt++)
        #pragma unroll
        for (int nt = 0; nt < 8; nt++)
            #pragma unroll
            for (int j = 0; j < 4; j++) acc[mt][nt][j] = 0.f;

    // smem fragment offsets (halves), hoisted
    const uint32_t fa0 = (uint32_t)((wm + g) * 32 + 8 * tg);
    const uint32_t fb0 = (uint32_t)((wn + g) * 32 + 8 * tg);

    #pragma unroll
    for (int p = 0; p < 3; p++) {          // prologue stages 0,1,2
        if (p < S) {
            uint32_t st = sbase + p * STAGEB;
            cp16(st + sAo,  gA0 + p * 32);
            cp16(st + sA1o, gA1 + p * 32);
            cp16(st + sBo,  gB0 + p * 32);
            cp16(st + sB1o, gB1 + p * 32);
        }
        asm volatile("cp.async.commit_group;" ::: "memory");
    }

    #pragma unroll
    for (int s = 0; s < S; s++) {
        asm volatile("cp.async.wait_group 2;" ::: "memory");
        __syncthreads();

        if (s + 3 < S) {
            uint32_t st = sbase + ((s + 3) % NSTG) * STAGEB;   // compile-time folded
            cp16(st + sAo,  gA0 + (s + 3) * 32);
            cp16(st + sA1o, gA1 + (s + 3) * 32);
            cp16(st + sBo,  gB0 + (s + 3) * 32);
            cp16(st + sB1o, gB1 + (s + 3) * 32);
        }
        asm volatile("cp.async.commit_group;" ::: "memory");

        const __half* As = (const __half*)(smem + (s % NSTG) * STAGEB);
        const __half* Bs = As + TILEB / 2;

        uint4 a0[2], a1[2];
        #pragma unroll
        for (int mt = 0; mt < 2; mt++) {
            a0[mt] = *(const uint4*)(As + fa0 + mt * 16 * 32);
            a1[mt] = *(const uint4*)(As + fa0 + mt * 16 * 32 + 8 * 32);
        }
        #pragma unroll
        for (int nt = 0; nt < 8; nt++) {
            uint4 bv = *(const uint4*)(Bs + fb0 + nt * 8 * 32);
            #pragma unroll
            for (int mt = 0; mt < 2; mt++) {
                MMA_F16(acc[mt][nt], a0[mt].x, a1[mt].x, a0[mt].y, a1[mt].y, bv.x, bv.y);
                MMA_F16(acc[mt][nt], a0[mt].z, a1[mt].z, a0[mt].w, a1[mt].w, bv.z, bv.w);
            }
        }
        __syncthreads();
    }

    // epilogue: c0,c1 -> row g cols 2tg,2tg+1; c2,c3 -> row g+8
    if (EPI == 0 || blockIdx.z == 1) {
        #pragma unroll
        for (int mt = 0; mt < 2; mt++) {
            int gm0 = bm + wm + mt * 16 + g;
            #pragma unroll
            for (int nt = 0; nt < 8; nt++) {
                int gn = bn + wn + nt * 8 + 2 * tg;
                float b0 = bias[gn], b1 = bias[gn + 1];
                float v0 = acc[mt][nt][0] + b0;
                float v1 = acc[mt][nt][1] + b1;
                float v2 = acc[mt][nt][2] + b0;
                float v3 = acc[mt][nt][3] + b1;
                if (EPI == 0) {
                    v0 = fmaxf(v0, 0.f); v1 = fmaxf(v1, 0.f);
                    v2 = fmaxf(v2, 0.f); v3 = fmaxf(v3, 0.f);
                } else {
                    float2 m0v = __half22float2(*(const __half2*)(mul + (size_t)gm0 * ldmul + gn));
                    float2 m1v = __half22float2(*(const __half2*)(mul + (size_t)(gm0 + 8) * ldmul + gn));
                    v0 *= m0v.x; v1 *= m0v.y; v2 *= m1v.x; v3 *= m1v.y;
                }
                *(__half2*)(C + (size_t)gm0 * N + gn) = __floats2half2_rn(v0, v1);
                *(__half2*)(C + (size_t)(gm0 + 8) * N + gn) = __floats2half2_rn(v2, v3);
            }
        }
    } else {
        // EPI==2, z==0 (k-side): fused attention dot, no store
        #pragma unroll
        for (int mt = 0; mt < 2; mt++) {
            int gm0 = bm + wm + mt * 16 + g;
            const float* q0 = g_QRYp + (size_t)(gm0 >> 2) * CKP;
            const float* q1 = g_QRYp + (size_t)((gm0 + 8) >> 2) * CKP;
            float dot0 = 0.f, dot1 = 0.f;
            #pragma unroll
            for (int nt = 0; nt < 8; nt++) {
                int gn = bn + wn + nt * 8 + 2 * tg;
                float b0 = bias[gn], b1 = bias[gn + 1];
                float2 m0v = __half22float2(*(const __half2*)(mul + (size_t)gm0 * ldmul + gn));
                float2 m1v = __half22float2(*(const __half2*)(mul + (size_t)(gm0 + 8) * ldmul + gn));
                float v0 = (acc[mt][nt][0] + b0) * m0v.x;
                float v1 = (acc[mt][nt][1] + b1) * m0v.y;
                float v2 = (acc[mt][nt][2] + b0) * m1v.x;
                float v3 = (acc[mt][nt][3] + b1) * m1v.y;
                float2 qa = *(const float2*)(q0 + gn);
                float2 qb = *(const float2*)(q1 + gn);
                dot0 += v0 * qa.x + v1 * qa.y;
                dot1 += v2 * qb.x + v3 * qb.y;
            }
            dot0 += __shfl_xor_sync(0xffffffffu, dot0, 1);
            dot0 += __shfl_xor_sync(0xffffffffu, dot0, 2);
            dot1 += __shfl_xor_sync(0xffffffffu, dot1, 1);
            dot1 += __shfl_xor_sync(0xffffffffu, dot1, 2);
            if (tg == 0) {
                atomicAdd(&g_attn[gm0], dot0);
                atomicAdd(&g_attn[gm0 + 8], dot1);
            }
        }
    }
}

// ---------------- softmax over the 4 shifts --------------------------------
__global__ __launch_bounds__(256) void softmax_kernel() {
    int bq = blockIdx.x * 256 + threadIdx.x;     // 8192 threads
    float4 a = *(const float4*)&g_attn[bq * 4];
    float m = fmaxf(fmaxf(a.x, a.y), fmaxf(a.z, a.w));
    float e0 = expf(a.x - m), e1 = expf(a.y - m), e2 = expf(a.z - m), e3 = expf(a.w - m);
    float inv = 1.0f / (e0 + e1 + e2 + e3);
    float4 w = {e0 * inv, e1 * inv, e2 * inv, e3 * inv};
    *(float4*)&g_W[bq * 4] = w;
}

// ---------------- weighted PV sum -> X -------------------------------------
__global__ __launch_bounds__(160) void attnw_kernel() {
    const int bq = blockIdx.x;
    const int tid = threadIdx.x;
    if (tid < 144) {                       // CK/4 = 144, 4 halves per thread
        float4 w = *(const float4*)&g_W[bq * 4];
        const __half* pv = g_PVh + (size_t)bq * 4 * CKP;
        float x0 = 0.f, x1 = 0.f, x2 = 0.f, x3 = 0.f;
        float ws[4] = {w.x, w.y, w.z, w.w};
        #pragma unroll
        for (int s = 0; s < 4; s++) {
            uint2 u = *(const uint2*)(pv + (size_t)s * CKP + tid * 4);
            float2 f0 = __half22float2(*(__half2*)&u.x);
            float2 f1 = __half22float2(*(__half2*)&u.y);
            x0 += ws[s] * f0.x; x1 += ws[s] * f0.y;
            x2 += ws[s] * f1.x; x3 += ws[s] * f1.y;
        }
        __half2* xp = (__half2*)(g_Xh + (size_t)bq * CK);
        xp[tid * 2 + 0] = __floats2half2_rn(x0, x1);
        xp[tid * 2 + 1] = __floats2half2_rn(x2, x3);
    }
}

// ---------------- final projection: [8192,256] @ [256,3] + bias ------------
__global__ __launch_bounds__(128) void outproj_kernel(
    const float* __restrict__ qW2, const float* __restrict__ qb2,
    float* __restrict__ out) {
    int warp = threadIdx.x >> 5, lane = threadIdx.x & 31;
    int row = blockIdx.x * 4 + warp;
    const __half* h = g_Hqh + (size_t)row * HID;
    float a0 = 0.f, a1 = 0.f, a2 = 0.f;
    #pragma unroll
    for (int i = 0; i < 8; i++) {
        int k = i * 32 + lane;
        float a = __half2float(h[k]);
        a0 += a * qW2[k * 3 + 0];
        a1 += a * qW2[k * 3 + 1];
        a2 += a * qW2[k * 3 + 2];
    }
    #pragma unroll
    for (int off = 16; off; off >>= 1) {
        a0 += __shfl_down_sync(0xffffffffu, a0, off);
        a1 += __shfl_down_sync(0xffffffffu, a1, off);
        a2 += __shfl_down_sync(0xffffffffu, a2, off);
    }
    if (lane == 0) {
        out[row * 3 + 0] = a0 + qb2[0];
        out[row * 3 + 1] = a1 + qb2[1];
        out[row * 3 + 2] = a2 + qb2[2];
    }
}

// ---------------- launch ---------------------------------------------------
extern "C" void kernel_launch(void* const* d_in, const int* in_sizes, int n_in,
                              void* d_out, int out_size) {
    const float* feature = (const float*)d_in[0];
    const float* coord   = (const float*)d_in[1];
    const float* scale   = (const float*)d_in[2];
    const float* kW1 = (const float*)d_in[3];
    const float* kb1 = (const float*)d_in[4];
    const float* kW2 = (const float*)d_in[5];
    const float* kb2 = (const float*)d_in[6];
    const float* vW1 = (const float*)d_in[7];
    const float* vb1 = (const float*)d_in[8];
    const float* vW2 = (const float*)d_in[9];
    const float* vb2 = (const float*)d_in[10];
    const float* qW1 = (const float*)d_in[11];
    const float* qb1 = (const float*)d_in[12];
    const float* qW2 = (const float*)d_in[13];
    const float* qb2 = (const float*)d_in[14];
    float* out = (float*)d_out;

    __half *pINP, *pH, *pPV, *pX, *pHq, *pW1t, *pkW2t, *pvW2t, *pqW1t;
    float *pb1, *pkb2p, *pvb2p;
    cudaGetSymbolAddress((void**)&pINP,  g_INPh);
    cudaGetSymbolAddress((void**)&pH,    g_Hh);
    cudaGetSymbolAddress((void**)&pPV,   g_PVh);
    cudaGetSymbolAddress((void**)&pX,    g_Xh);
    cudaGetSymbolAddress((void**)&pHq,   g_Hqh);
    cudaGetSymbolAddress((void**)&pW1t,  g_W1t);
    cudaGetSymbolAddress((void**)&pb1,   g_b1);
    cudaGetSymbolAddress((void**)&pkW2t, g_kW2t);
    cudaGetSymbolAddress((void**)&pvW2t, g_vW2t);
    cudaGetSymbolAddress((void**)&pkb2p, g_kb2p);
    cudaGetSymbolAddress((void**)&pvb2p, g_vb2p);
    cudaGetSymbolAddress((void**)&pqW1t, g_qW1t);

    cudaFuncSetAttribute(mma_gemm<0, 19>, cudaFuncAttributeMaxDynamicSharedMemorySize, SMEMB);
    cudaFuncSetAttribute(mma_gemm<2, 8>,  cudaFuncAttributeMaxDynamicSharedMemorySize, SMEMB);
    cudaFuncSetAttribute(mma_gemm<0, 18>, cudaFuncAttributeMaxDynamicSharedMemorySize, SMEMB);

    // 0) transpose/pad weights -> fp16
    prep_weights<<<(512 * KINP + 255) / 256, 256>>>(kW1, vW1, kW2, vW2, qW1,
                                                    kb1, vb1, kb2, vb2);

    // 1) gather/setup (also zeros g_attn + query pad)
    setup_kernel<<<NROW, 128>>>(feature, coord, scale);

    // 2) fused layer-1:  H[:, 0:512] = relu(INP @ W1t^T + b1), K=608, N=512
    {
        dim3 grid(4, NROW4 / 128, 1);
        mma_gemm<0, 19><<<grid, 256, SMEMB>>>(pINP, pINP, KINP, pW1t, pW1t, pH, pH,
                                              pb1, pb1, nullptr, 0, 512);
    }

    // 3) layer-2 merged: z=0 k-side (fused dot -> g_attn, no store),
    //                    z=1 v-side (PV store). K=256, N=640.
    {
        dim3 grid(CKP / 128, NROW4 / 128, 2);
        mma_gemm<2, 8><<<grid, 256, SMEMB>>>(pH, pH + 256, 512, pkW2t, pvW2t,
                                             pPV, pPV, pkb2p, pvb2p,
                                             pINP, KINP, CKP);
    }

    // 4) softmax over shifts, then weighted PV sum -> X
    softmax_kernel<<<NROW / 256, 256>>>();
    attnw_kernel<<<NROW, 160>>>();

    // 5) query MLP layer 1: Hq = relu(X @ qW1t^T + qb1), K=576, N=256
    {
        dim3 grid(2, NROW / 128, 1);
        mma_gemm<0, 18><<<grid, 256, SMEMB>>>(pX, pX, CK, pqW1t, pqW1t, pHq, pHq,
                                              qb1, qb1, nullptr, 0, 256);
    }

    // 6) output projection  [8192 x 3]
    outproj_kernel<<<NROW / 4, 128>>>(qW2, qb2, out);
}

// round 16
// speedup vs baseline: 1.3932x; 1.0940x over previous
#include <cuda_runtime.h>
#include <cuda_fp16.h>
#include <math.h>
#include <stdint.h>

// Problem constants
#define BB 2
#define QQ 4096
#define CC 64
#define HH 64
#define WW 64
#define CK 576          // C*9
#define KIN 580         // CK + 4
#define KINP 608        // K padding for layer-1 (mult of 32)
#define CKP 640         // N padding for layer-2 (mult of 128)
#define HID 256
#define NROW (BB*QQ)        // 8192
#define NROW4 (BB*QQ*4)     // 32768

// CK-space permutation: k' = p*64 + c  (orig k = c*9 + p)
// applied to: INP cols, W1t cols, QRY cols, W2 rows, b2, qW1t cols.

// ---------------- scratch (device globals; no allocation) ----------------
__device__ float  g_featT[BB * 4096 * CC];    // [B,H*W,C] transposed feature
__device__ __half g_INPh[NROW4 * KINP + 64];  // [32768, 608] permuted cols
__device__ float  g_QRYp[NROW * CKP];         // [8192, 640] fp32 permuted, cols 576.. zero
__device__ __half g_Hh  [NROW4 * 512];        // cols 0..255 Hk, 256..511 Hv
__device__ __half g_PVh [NROW4 * CKP];        // stride 640 (permuted N space)
__device__ float  g_attn[NROW4];              // fused dot accumulators
__device__ float  g_W   [NROW4];              // softmax weights (4 per bq)
__device__ __half g_Xh  [NROW * CK];          // permuted cols
__device__ __half g_Hqh [NROW * HID];
// weights, [N, K] K-major, fp16
__device__ __half g_W1t [512 * KINP];         // cols permuted
__device__ float  g_b1  [512];
__device__ __half g_kW2t[CKP * HID];          // rows permuted; 576..639 zero
__device__ __half g_vW2t[CKP * HID];
__device__ float  g_kb2p[CKP];                // permuted padded biases
__device__ float  g_vb2p[CKP];
__device__ __half g_qW1t[HID * CK];           // cols permuted

__device__ __forceinline__ uint32_t s2u(const void* p) {
    uint32_t a;
    asm("{ .reg .u64 t; cvta.to.shared.u64 t, %1; cvt.u32.u64 %0, t; }" : "=r"(a) : "l"(p));
    return a;
}

// ---------------- feature transpose [B,C,HW] -> [B,HW,C] --------------------
__global__ __launch_bounds__(256) void transpose_feat(const float* __restrict__ f) {
    __shared__ float t[32][33];
    int b  = blockIdx.z;
    int c0 = blockIdx.y * 32;
    int p0 = blockIdx.x * 32;
    int tx = threadIdx.x & 31, ty = threadIdx.x >> 5;   // 32 x 8
    const float* fb = f + (size_t)b * CC * 4096;
    #pragma unroll
    for (int i = 0; i < 32; i += 8)
        t[ty + i][tx] = fb[(size_t)(c0 + ty + i) * 4096 + p0 + tx];
    __syncthreads();
    float* ob = g_featT + (size_t)b * 4096 * CC;
    #pragma unroll
    for (int i = 0; i < 32; i += 8)
        ob[(size_t)(p0 + ty + i) * CC + c0 + tx] = t[tx][ty + i];
}

// ---------------- weight transpose / pad / permute / fp16 -------------------
__global__ void prep_weights(const float* __restrict__ kW1, const float* __restrict__ vW1,
                             const float* __restrict__ kW2, const float* __restrict__ vW2,
                             const float* __restrict__ qW1,
                             const float* __restrict__ kb1, const float* __restrict__ vb1,
                             const float* __restrict__ kb2, const float* __restrict__ vb2) {
    int i = blockIdx.x * 256 + threadIdx.x;
    if (i < 512 * KINP) {           // fused W1: [512, 608], cols permuted
        int n = i / KINP, kp = i - n * KINP;
        int ko = (kp < CK) ? ((kp & 63) * 9 + (kp >> 6)) : kp;   // orig K index
        float v = 0.f;
        if (ko < KIN) v = (n < HID) ? kW1[ko * HID + n] : vW1[ko * HID + (n - HID)];
        g_W1t[i] = __float2half_rn(v);
    }
    if (i < CKP * HID) {            // [640, 256]: rows = permuted CK space
        int np = i / HID, k = i - np * HID;
        float a = 0.f, b = 0.f;
        if (np < CK) {
            int no = (np & 63) * 9 + (np >> 6);
            a = kW2[k * CK + no]; b = vW2[k * CK + no];
        }
        g_kW2t[i] = __float2half_rn(a);
        g_vW2t[i] = __float2half_rn(b);
    }
    if (i < HID * CK) {             // [256, 576]: cols permuted
        int n = i / CK, kp = i - n * CK;
        int ko = (kp & 63) * 9 + (kp >> 6);
        g_qW1t[i] = __float2half_rn(qW1[ko * HID + n]);
    }
    if (i < 512)
        g_b1[i] = (i < HID) ? kb1[i] : vb1[i - HID];
    if (i < CKP) {
        float a = 0.f, b = 0.f;
        if (i < CK) {
            int no = (i & 63) * 9 + (i >> 6);
            a = kb2[no]; b = vb2[no];
        }
        g_kb2p[i] = a; g_vb2p[i] = b;
    }
}

// ---------------- setup: coalesced gather, build INP + query ----------------
__device__ __forceinline__ int nearest_idx(float c) {
    float f = ((c + 1.0f) * 64.0f - 1.0f) * 0.5f + 0.5f;
    int i = (int)floorf(f);
    return i < 0 ? 0 : (i > 63 ? 63 : i);
}

__global__ __launch_bounds__(128) void setup_kernel(
    const float* __restrict__ coord, const float* __restrict__ scale) {
    const int bq = blockIdx.x;
    const int b  = bq >> 12;
    const int tid = threadIdx.x;

    const float cy = coord[bq * 2 + 0];
    const float cx = coord[bq * 2 + 1];
    const float s0 = scale[bq * 2 + 0];
    const float s1 = scale[bq * 2 + 1];
    const float lo = -1.0f + 1e-6f, hi = 1.0f - 1e-6f;

    int   qy[4], qx[4];
    float area[4];
    const float rx = 1.0f / 64.0f, ry = 1.0f / 64.0f;
    #pragma unroll
    for (int s = 0; s < 4; s++) {
        float vx = (s >= 2) ? 1.0f : -1.0f;
        float vy = (s & 1)  ? 1.0f : -1.0f;
        float c0 = fminf(fmaxf(cy + vx * rx + 1e-6f, lo), hi);
        float c1 = fminf(fmaxf(cx + vy * ry + 1e-6f, lo), hi);
        int iy = nearest_idx(c0), ix = nearest_idx(c1);
        qy[s] = iy; qx[s] = ix;
        float qc0 = -1.0f + (2.0f * iy + 1.0f) / 64.0f;
        float qc1 = -1.0f + (2.0f * ix + 1.0f) / 64.0f;
        area[s] = fabsf((cy - qc0) * 64.0f * (cx - qc1) * 64.0f) + 1e-9f;
    }
    float tot = area[0] + area[1] + area[2] + area[3];
    float qw[4];
    #pragma unroll
    for (int s = 0; s < 4; s++) qw[s] = area[3 - s] / tot;

    const float sc00 = scale[(b * QQ) * 2 + 0];
    const float sc01 = scale[(b * QQ) * 2 + 1];
    const float invtx = (1.0f - sc00) / 63.0f;
    const float invty = (1.0f - sc01) / 63.0f;
    int   ky[4], kx[4];
    float kr0[4], kr1[4];
    #pragma unroll
    for (int s = 0; s < 4; s++) {
        float vx = (s >= 2) ? 1.0f : -1.0f;
        float vy = (s & 1)  ? 1.0f : -1.0f;
        float c0 = fminf(fmaxf(cy + vx * invtx + 1e-6f, lo), hi);
        float c1 = fminf(fmaxf(cx + vy * invty + 1e-6f, lo), hi);
        int iy = nearest_idx(c0), ix = nearest_idx(c1);
        ky[s] = iy; kx[s] = ix;
        float qc0 = -1.0f + (2.0f * iy + 1.0f) / 64.0f;
        float qc1 = -1.0f + (2.0f * ix + 1.0f) / 64.0f;
        kr0[s] = (cy - qc0) * 64.0f;
        kr1[s] = (cx - qc1) * 64.0f;
    }

    // permuted gather: k' = p*64 + c, reads coalesced in c
    const float* ft = g_featT + (size_t)b * 4096 * CC;
    for (int kp = tid; kp < CK; kp += 128) {
        int p = kp >> 6, c = kp & 63;
        int di = p / 3 - 1, dj = p - (p / 3) * 3 - 1;
        float qacc = 0.f;
        #pragma unroll
        for (int s = 0; s < 4; s++) {
            int y = qy[s] + di, x = qx[s] + dj;
            float v = ((unsigned)y < 64u && (unsigned)x < 64u)
                      ? ft[(size_t)(y * 64 + x) * CC + c] : 0.f;
            qacc += qw[s] * v;
        }
        g_QRYp[(size_t)bq * CKP + kp] = qacc;
        #pragma unroll
        for (int s = 0; s < 4; s++) {
            int y = ky[s] + di, x = kx[s] + dj;
            float v = ((unsigned)y < 64u && (unsigned)x < 64u)
                      ? ft[(size_t)(y * 64 + x) * CC + c] : 0.f;
            g_INPh[((size_t)(bq * 4 + s)) * KINP + kp] = __float2half_rn(v);
        }
    }
    if (tid < 64)        // zero query pad cols 576..639
        g_QRYp[(size_t)bq * CKP + CK + tid] = 0.f;
    if (tid < 4)         // zero attn accumulators (re-zeroed every launch)
        g_attn[bq * 4 + tid] = 0.f;
    {   // cols 576..607: rel(2), scale(2), zeros. 128 thr = 4 shifts x 32 cols.
        int s = tid >> 5, cc = tid & 31;
        float v = 0.f;
        if (cc == 0) v = kr0[s];
        else if (cc == 1) v = kr1[s];
        else if (cc == 2) v = s0 * 64.0f;
        else if (cc == 3) v = s1 * 64.0f;
        g_INPh[((size_t)(bq * 4 + s)) * KINP + 576 + cc] = __float2half_rn(v);
    }
}

// ---------------- fp16 mma.sync GEMM (compile-time K, 4-stage) --------------
// Unchanged from the 262us baseline.
#define TILEB 8192
#define STAGEB 16384
#define NSTG 4
#define SMEMB (NSTG*STAGEB)         // 65536

__device__ __forceinline__ void cp16(uint32_t dst, const __half* src) {
    asm volatile("cp.async.cg.shared.global [%0], [%1], 16;" :: "r"(dst), "l"(src) : "memory");
}
#define MMA_F16(acc, a0, a1, a2, a3, b0, b1)                                     \
    asm volatile("mma.sync.aligned.m16n8k16.row.col.f32.f16.f16.f32 "            \
        "{%0,%1,%2,%3}, {%4,%5,%6,%7}, {%8,%9}, {%0,%1,%2,%3};"                  \
        : "+f"((acc)[0]), "+f"((acc)[1]), "+f"((acc)[2]), "+f"((acc)[3])         \
        : "r"(a0), "r"(a1), "r"(a2), "r"(a3), "r"(b0), "r"(b1))

template<int EPI, int S>
__global__ __launch_bounds__(256, 2) void mma_gemm(
    const __half* __restrict__ A0, const __half* __restrict__ A1, int lda,
    const __half* __restrict__ B0, const __half* __restrict__ B1,
    __half* __restrict__ C0, __half* __restrict__ C1,
    const float* __restrict__ bias0, const float* __restrict__ bias1,
    const __half* __restrict__ mul, int ldmul, int N) {
    extern __shared__ char smem[];
    constexpr int K = 32 * S;
    const int tid = threadIdx.x;
    const int lane = tid & 31, wid = tid >> 5;
    const int g = lane >> 2, tg = lane & 3;
    const int wm = (wid & 3) * 32, wn = (wid >> 2) * 64;
    const int bm = blockIdx.y * 128, bn = blockIdx.x * 128;
    const uint32_t sbase = s2u(smem);

    const __half* A = blockIdx.z ? A1 : A0;
    const __half* B = blockIdx.z ? B1 : B0;
    __half*       C = blockIdx.z ? C1 : C0;
    const float* bias = blockIdx.z ? bias1 : bias0;

    const int ldrow = tid >> 2, ldq = tid & 3;
    const __half* gA0 = A + (size_t)(bm + ldrow) * lda + ldq * 8;
    const __half* gA1 = A + (size_t)(bm + ldrow + 64) * lda + ldq * 8;
    const __half* gB0 = B + (size_t)(bn + ldrow) * K + ldq * 8;
    const __half* gB1 = B + (size_t)(bn + ldrow + 64) * K + ldq * 8;
    const uint32_t sAo = (uint32_t)(ldrow * 64 + ldq * 16);
    const uint32_t sBo = sAo + TILEB;
    const uint32_t sA1o = sAo + 64 * 64;
    const uint32_t sB1o = sBo + 64 * 64;

    float acc[2][8][4];
    #pragma unroll
    for (int mt = 0; mt < 2; mt++)
        #pragma unroll
        for (int nt = 0; nt < 8; nt++)
            #pragma unroll
            for (int j = 0; j < 4; j++) acc[mt][nt][j] = 0.f;

    const uint32_t fa0 = (uint32_t)((wm + g) * 32 + 8 * tg);
    const uint32_t fb0 = (uint32_t)((wn + g) * 32 + 8 * tg);

    #pragma unroll
    for (int p = 0; p < 3; p++) {
        if (p < S) {
            uint32_t st = sbase + p * STAGEB;
            cp16(st + sAo,  gA0 + p * 32);
            cp16(st + sA1o, gA1 + p * 32);
            cp16(st + sBo,  gB0 + p * 32);
            cp16(st + sB1o, gB1 + p * 32);
        }
        asm volatile("cp.async.commit_group;" ::: "memory");
    }

    #pragma unroll
    for (int s = 0; s < S; s++) {
        asm volatile("cp.async.wait_group 2;" ::: "memory");
        __syncthreads();

        if (s + 3 < S) {
            uint32_t st = sbase + ((s + 3) % NSTG) * STAGEB;
            cp16(st + sAo,  gA0 + (s + 3) * 32);
            cp16(st + sA1o, gA1 + (s + 3) * 32);
            cp16(st + sBo,  gB0 + (s + 3) * 32);
            cp16(st + sB1o, gB1 + (s + 3) * 32);
        }
        asm volatile("cp.async.commit_group;" ::: "memory");

        const __half* As = (const __half*)(smem + (s % NSTG) * STAGEB);
        const __half* Bs = As + TILEB / 2;

        uint4 a0[2], a1[2];
        #pragma unroll
        for (int mt = 0; mt < 2; mt++) {
            a0[mt] = *(const uint4*)(As + fa0 + mt * 16 * 32);
            a1[mt] = *(const uint4*)(As + fa0 + mt * 16 * 32 + 8 * 32);
        }
        #pragma unroll
        for (int nt = 0; nt < 8; nt++) {
            uint4 bv = *(const uint4*)(Bs + fb0 + nt * 8 * 32);
            #pragma unroll
            for (int mt = 0; mt < 2; mt++) {
                MMA_F16(acc[mt][nt], a0[mt].x, a1[mt].x, a0[mt].y, a1[mt].y, bv.x, bv.y);
                MMA_F16(acc[mt][nt], a0[mt].z, a1[mt].z, a0[mt].w, a1[mt].w, bv.z, bv.w);
            }
        }
        __syncthreads();
    }

    if (EPI == 0 || blockIdx.z == 1) {
        #pragma unroll
        for (int mt = 0; mt < 2; mt++) {
            int gm0 = bm + wm + mt * 16 + g;
            #pragma unroll
            for (int nt = 0; nt < 8; nt++) {
                int gn = bn + wn + nt * 8 + 2 * tg;
                float b0 = bias[gn], b1 = bias[gn + 1];
                float v0 = acc[mt][nt][0] + b0;
                float v1 = acc[mt][nt][1] + b1;
                float v2 = acc[mt][nt][2] + b0;
                float v3 = acc[mt][nt][3] + b1;
                if (EPI == 0) {
                    v0 = fmaxf(v0, 0.f); v1 = fmaxf(v1, 0.f);
                    v2 = fmaxf(v2, 0.f); v3 = fmaxf(v3, 0.f);
                } else {
                    float2 m0v = __half22float2(*(const __half2*)(mul + (size_t)gm0 * ldmul + gn));
                    float2 m1v = __half22float2(*(const __half2*)(mul + (size_t)(gm0 + 8) * ldmul + gn));
                    v0 *= m0v.x; v1 *= m0v.y; v2 *= m1v.x; v3 *= m1v.y;
                }
                *(__half2*)(C + (size_t)gm0 * N + gn) = __floats2half2_rn(v0, v1);
                *(__half2*)(C + (size_t)(gm0 + 8) * N + gn) = __floats2half2_rn(v2, v3);
            }
        }
    } else {
        #pragma unroll
        for (int mt = 0; mt < 2; mt++) {
            int gm0 = bm + wm + mt * 16 + g;
            const float* q0 = g_QRYp + (size_t)(gm0 >> 2) * CKP;
            const float* q1 = g_QRYp + (size_t)((gm0 + 8) >> 2) * CKP;
            float dot0 = 0.f, dot1 = 0.f;
            #pragma unroll
            for (int nt = 0; nt < 8; nt++) {
                int gn = bn + wn + nt * 8 + 2 * tg;
                float b0 = bias[gn], b1 = bias[gn + 1];
                float2 m0v = __half22float2(*(const __half2*)(mul + (size_t)gm0 * ldmul + gn));
                float2 m1v = __half22float2(*(const __half2*)(mul + (size_t)(gm0 + 8) * ldmul + gn));
                float v0 = (acc[mt][nt][0] + b0) * m0v.x;
                float v1 = (acc[mt][nt][1] + b1) * m0v.y;
                float v2 = (acc[mt][nt][2] + b0) * m1v.x;
                float v3 = (acc[mt][nt][3] + b1) * m1v.y;
                float2 qa = *(const float2*)(q0 + gn);
                float2 qb = *(const float2*)(q1 + gn);
                dot0 += v0 * qa.x + v1 * qa.y;
                dot1 += v2 * qb.x + v3 * qb.y;
            }
            dot0 += __shfl_xor_sync(0xffffffffu, dot0, 1);
            dot0 += __shfl_xor_sync(0xffffffffu, dot0, 2);
            dot1 += __shfl_xor_sync(0xffffffffu, dot1, 1);
            dot1 += __shfl_xor_sync(0xffffffffu, dot1, 2);
            if (tg == 0) {
                atomicAdd(&g_attn[gm0], dot0);
                atomicAdd(&g_attn[gm0 + 8], dot1);
            }
        }
    }
}

// ---------------- softmax over the 4 shifts --------------------------------
__global__ __launch_bounds__(256) void softmax_kernel() {
    int bq = blockIdx.x * 256 + threadIdx.x;     // 8192 threads
    float4 a = *(const float4*)&g_attn[bq * 4];
    float m = fmaxf(fmaxf(a.x, a.y), fmaxf(a.z, a.w));
    float e0 = expf(a.x - m), e1 = expf(a.y - m), e2 = expf(a.z - m), e3 = expf(a.w - m);
    float inv = 1.0f / (e0 + e1 + e2 + e3);
    float4 w = {e0 * inv, e1 * inv, e2 * inv, e3 * inv};
    *(float4*)&g_W[bq * 4] = w;
}

// ---------------- weighted PV sum -> X -------------------------------------
__global__ __launch_bounds__(160) void attnw_kernel() {
    const int bq = blockIdx.x;
    const int tid = threadIdx.x;
    if (tid < 144) {
        float4 w = *(const float4*)&g_W[bq * 4];
        const __half* pv = g_PVh + (size_t)bq * 4 * CKP;
        float x0 = 0.f, x1 = 0.f, x2 = 0.f, x3 = 0.f;
        float ws[4] = {w.x, w.y, w.z, w.w};
        #pragma unroll
        for (int s = 0; s < 4; s++) {
            uint2 u = *(const uint2*)(pv + (size_t)s * CKP + tid * 4);
            float2 f0 = __half22float2(*(__half2*)&u.x);
            float2 f1 = __half22float2(*(__half2*)&u.y);
            x0 += ws[s] * f0.x; x1 += ws[s] * f0.y;
            x2 += ws[s] * f1.x; x3 += ws[s] * f1.y;
        }
        __half2* xp = (__half2*)(g_Xh + (size_t)bq * CK);
        xp[tid * 2 + 0] = __floats2half2_rn(x0, x1);
        xp[tid * 2 + 1] = __floats2half2_rn(x2, x3);
    }
}

// ---------------- final projection: [8192,256] @ [256,3] + bias ------------
__global__ __launch_bounds__(128) void outproj_kernel(
    const float* __restrict__ qW2, const float* __restrict__ qb2,
    float* __restrict__ out) {
    int warp = threadIdx.x >> 5, lane = threadIdx.x & 31;
    int row = blockIdx.x * 4 + warp;
    const __half* h = g_Hqh + (size_t)row * HID;
    float a0 = 0.f, a1 = 0.f, a2 = 0.f;
    #pragma unroll
    for (int i = 0; i < 8; i++) {
        int k = i * 32 + lane;
        float a = __half2float(h[k]);
        a0 += a * qW2[k * 3 + 0];
        a1 += a * qW2[k * 3 + 1];
        a2 += a * qW2[k * 3 + 2];
    }
    #pragma unroll
    for (int off = 16; off; off >>= 1) {
        a0 += __shfl_down_sync(0xffffffffu, a0, off);
        a1 += __shfl_down_sync(0xffffffffu, a1, off);
        a2 += __shfl_down_sync(0xffffffffu, a2, off);
    }
    if (lane == 0) {
        out[row * 3 + 0] = a0 + qb2[0];
        out[row * 3 + 1] = a1 + qb2[1];
        out[row * 3 + 2] = a2 + qb2[2];
    }
}

// ---------------- launch ---------------------------------------------------
extern "C" void kernel_launch(void* const* d_in, const int* in_sizes, int n_in,
                              void* d_out, int out_size) {
    const float* feature = (const float*)d_in[0];
    const float* coord   = (const float*)d_in[1];
    const float* scale   = (const float*)d_in[2];
    const float* kW1 = (const float*)d_in[3];
    const float* kb1 = (const float*)d_in[4];
    const float* kW2 = (const float*)d_in[5];
    const float* kb2 = (const float*)d_in[6];
    const float* vW1 = (const float*)d_in[7];
    const float* vb1 = (const float*)d_in[8];
    const float* vW2 = (const float*)d_in[9];
    const float* vb2 = (const float*)d_in[10];
    const float* qW1 = (const float*)d_in[11];
    const float* qb1 = (const float*)d_in[12];
    const float* qW2 = (const float*)d_in[13];
    const float* qb2 = (const float*)d_in[14];
    float* out = (float*)d_out;

    __half *pINP, *pH, *pPV, *pX, *pHq, *pW1t, *pkW2t, *pvW2t, *pqW1t;
    float *pb1, *pkb2p, *pvb2p;
    cudaGetSymbolAddress((void**)&pINP,  g_INPh);
    cudaGetSymbolAddress((void**)&pH,    g_Hh);
    cudaGetSymbolAddress((void**)&pPV,   g_PVh);
    cudaGetSymbolAddress((void**)&pX,    g_Xh);
    cudaGetSymbolAddress((void**)&pHq,   g_Hqh);
    cudaGetSymbolAddress((void**)&pW1t,  g_W1t);
    cudaGetSymbolAddress((void**)&pb1,   g_b1);
    cudaGetSymbolAddress((void**)&pkW2t, g_kW2t);
    cudaGetSymbolAddress((void**)&pvW2t, g_vW2t);
    cudaGetSymbolAddress((void**)&pkb2p, g_kb2p);
    cudaGetSymbolAddress((void**)&pvb2p, g_vb2p);
    cudaGetSymbolAddress((void**)&pqW1t, g_qW1t);

    cudaFuncSetAttribute(mma_gemm<0, 19>, cudaFuncAttributeMaxDynamicSharedMemorySize, SMEMB);
    cudaFuncSetAttribute(mma_gemm<2, 8>,  cudaFuncAttributeMaxDynamicSharedMemorySize, SMEMB);
    cudaFuncSetAttribute(mma_gemm<0, 18>, cudaFuncAttributeMaxDynamicSharedMemorySize, SMEMB);

    // 0) feature transpose + weight prep
    {
        dim3 tg2(128, 2, BB);
        transpose_feat<<<tg2, 256>>>(feature);
        prep_weights<<<(512 * KINP + 255) / 256, 256>>>(kW1, vW1, kW2, vW2, qW1,
                                                        kb1, vb1, kb2, vb2);
    }

    // 1) gather/setup (coalesced; also zeros g_attn + query pad)
    setup_kernel<<<NROW, 128>>>(coord, scale);

    // 2) fused layer-1:  H[:, 0:512] = relu(INP @ W1t^T + b1), K=608, N=512
    {
        dim3 grid(4, NROW4 / 128, 1);
        mma_gemm<0, 19><<<grid, 256, SMEMB>>>(pINP, pINP, KINP, pW1t, pW1t, pH, pH,
                                              pb1, pb1, nullptr, 0, 512);
    }

    // 3) layer-2 merged: z=0 k-side (fused dot -> g_attn, no store),
    //                    z=1 v-side (PV store). K=256, N=640.
    {
        dim3 grid(CKP / 128, NROW4 / 128, 2);
        mma_gemm<2, 8><<<grid, 256, SMEMB>>>(pH, pH + 256, 512, pkW2t, pvW2t,
                                             pPV, pPV, pkb2p, pvb2p,
                                             pINP, KINP, CKP);
    }

    // 4) softmax over shifts, then weighted PV sum -> X
    softmax_kernel<<<NROW / 256, 256>>>();
    attnw_kernel<<<NROW, 160>>>();

    // 5) query MLP layer 1: Hq = relu(X @ qW1t^T + qb1), K=576, N=256
    {
        dim3 grid(2, NROW / 128, 1);
        mma_gemm<0, 18><<<grid, 256, SMEMB>>>(pX, pX, CK, pqW1t, pqW1t, pHq, pHq,
                                              qb1, qb1, nullptr, 0, 256);
    }

    // 6) output projection  [8192 x 3]
    outproj_kernel<<<NROW / 4, 128>>>(qW2, qb2, out);
}

// round 17
// speedup vs baseline: 1.4174x; 1.0174x over previous
#include <cuda_runtime.h>
#include <cuda_fp16.h>
#include <math.h>
#include <stdint.h>

// Problem constants
#define BB 2
#define QQ 4096
#define CC 64
#define HH 64
#define WW 64
#define CK 576          // C*9
#define KIN 580         // CK + 4
#define KINP 608        // K padding for layer-1 (mult of 32)
#define CKP 640         // N padding for layer-2 (mult of 128)
#define HID 256
#define NROW (BB*QQ)        // 8192
#define NROW4 (BB*QQ*4)     // 32768

// CK-space permutation: k' = p*64 + c  (orig k = c*9 + p)

// ---------------- scratch (device globals; no allocation) ----------------
__device__ float  g_featT[BB * 4096 * CC];    // [B,H*W,C] transposed feature
__device__ __half g_INPh[NROW4 * KINP + 64];  // [32768, 608] permuted cols
__device__ float  g_QRYp[NROW * CKP];         // [8192, 640] fp32 permuted, cols 576.. zero
__device__ __half g_Hh  [NROW4 * 512];        // cols 0..255 Hk, 256..511 Hv
__device__ __half g_PVh [NROW4 * CKP];        // stride 640 (permuted N space)
__device__ float  g_attn[NROW4];              // fused dot accumulators
__device__ __half g_Xh  [NROW * CK];          // permuted cols
// weights, [N, K] K-major, fp16
__device__ __half g_W1t [512 * KINP];         // cols permuted
__device__ float  g_b1  [512];
__device__ __half g_kW2t[CKP * HID];          // rows permuted; 576..639 zero
__device__ __half g_vW2t[CKP * HID];
__device__ float  g_kb2p[CKP];                // permuted padded biases
__device__ float  g_vb2p[CKP];
__device__ __half g_qW1t[HID * CK];           // cols permuted
__device__ float  g_qW2 [HID * 3];            // fp32 copy for fused outproj
__device__ float  g_qb2 [3];

__device__ __forceinline__ uint32_t s2u(const void* p) {
    uint32_t a;
    asm("{ .reg .u64 t; cvta.to.shared.u64 t, %1; cvt.u32.u64 %0, t; }" : "=r"(a) : "l"(p));
    return a;
}

// ---------------- feature transpose [B,C,HW] -> [B,HW,C] --------------------
__global__ __launch_bounds__(256) void transpose_feat(const float* __restrict__ f) {
    __shared__ float t[32][33];
    int b  = blockIdx.z;
    int c0 = blockIdx.y * 32;
    int p0 = blockIdx.x * 32;
    int tx = threadIdx.x & 31, ty = threadIdx.x >> 5;   // 32 x 8
    const float* fb = f + (size_t)b * CC * 4096;
    #pragma unroll
    for (int i = 0; i < 32; i += 8)
        t[ty + i][tx] = fb[(size_t)(c0 + ty + i) * 4096 + p0 + tx];
    __syncthreads();
    float* ob = g_featT + (size_t)b * 4096 * CC;
    #pragma unroll
    for (int i = 0; i < 32; i += 8)
        ob[(size_t)(p0 + ty + i) * CC + c0 + tx] = t[tx][ty + i];
}

// ---------------- weight transpose / pad / permute / fp16 -------------------
__global__ void prep_weights(const float* __restrict__ kW1, const float* __restrict__ vW1,
                             const float* __restrict__ kW2, const float* __restrict__ vW2,
                             const float* __restrict__ qW1,
                             const float* __restrict__ kb1, const float* __restrict__ vb1,
                             const float* __restrict__ kb2, const float* __restrict__ vb2,
                             const float* __restrict__ qW2, const float* __restrict__ qb2) {
    int i = blockIdx.x * 256 + threadIdx.x;
    if (i < 512 * KINP) {           // fused W1: [512, 608], cols permuted
        int n = i / KINP, kp = i - n * KINP;
        int ko = (kp < CK) ? ((kp & 63) * 9 + (kp >> 6)) : kp;
        float v = 0.f;
        if (ko < KIN) v = (n < HID) ? kW1[ko * HID + n] : vW1[ko * HID + (n - HID)];
        g_W1t[i] = __float2half_rn(v);
    }
    if (i < CKP * HID) {            // [640, 256]: rows = permuted CK space
        int np = i / HID, k = i - np * HID;
        float a = 0.f, b = 0.f;
        if (np < CK) {
            int no = (np & 63) * 9 + (np >> 6);
            a = kW2[k * CK + no]; b = vW2[k * CK + no];
        }
        g_kW2t[i] = __float2half_rn(a);
        g_vW2t[i] = __float2half_rn(b);
    }
    if (i < HID * CK) {             // [256, 576]: cols permuted
        int n = i / CK, kp = i - n * CK;
        int ko = (kp & 63) * 9 + (kp >> 6);
        g_qW1t[i] = __float2half_rn(qW1[ko * HID + n]);
    }
    if (i < 512)
        g_b1[i] = (i < HID) ? kb1[i] : vb1[i - HID];
    if (i < CKP) {
        float a = 0.f, b = 0.f;
        if (i < CK) {
            int no = (i & 63) * 9 + (i >> 6);
            a = kb2[no]; b = vb2[no];
        }
        g_kb2p[i] = a; g_vb2p[i] = b;
    }
    if (i < HID * 3) g_qW2[i] = qW2[i];
    if (i < 3)       g_qb2[i] = qb2[i];
}

// ---------------- setup: coalesced gather, build INP + query ----------------
__device__ __forceinline__ int nearest_idx(float c) {
    float f = ((c + 1.0f) * 64.0f - 1.0f) * 0.5f + 0.5f;
    int i = (int)floorf(f);
    return i < 0 ? 0 : (i > 63 ? 63 : i);
}

__global__ __launch_bounds__(128) void setup_kernel(
    const float* __restrict__ coord, const float* __restrict__ scale) {
    const int bq = blockIdx.x;
    const int b  = bq >> 12;
    const int tid = threadIdx.x;

    const float cy = coord[bq * 2 + 0];
    const float cx = coord[bq * 2 + 1];
    const float s0 = scale[bq * 2 + 0];
    const float s1 = scale[bq * 2 + 1];
    const float lo = -1.0f + 1e-6f, hi = 1.0f - 1e-6f;

    int   qy[4], qx[4];
    float area[4];
    const float rx = 1.0f / 64.0f, ry = 1.0f / 64.0f;
    #pragma unroll
    for (int s = 0; s < 4; s++) {
        float vx = (s >= 2) ? 1.0f : -1.0f;
        float vy = (s & 1)  ? 1.0f : -1.0f;
        float c0 = fminf(fmaxf(cy + vx * rx + 1e-6f, lo), hi);
        float c1 = fminf(fmaxf(cx + vy * ry + 1e-6f, lo), hi);
        int iy = nearest_idx(c0), ix = nearest_idx(c1);
        qy[s] = iy; qx[s] = ix;
        float qc0 = -1.0f + (2.0f * iy + 1.0f) / 64.0f;
        float qc1 = -1.0f + (2.0f * ix + 1.0f) / 64.0f;
        area[s] = fabsf((cy - qc0) * 64.0f * (cx - qc1) * 64.0f) + 1e-9f;
    }
    float tot = area[0] + area[1] + area[2] + area[3];
    float qw[4];
    #pragma unroll
    for (int s = 0; s < 4; s++) qw[s] = area[3 - s] / tot;

    const float sc00 = scale[(b * QQ) * 2 + 0];
    const float sc01 = scale[(b * QQ) * 2 + 1];
    const float invtx = (1.0f - sc00) / 63.0f;
    const float invty = (1.0f - sc01) / 63.0f;
    int   ky[4], kx[4];
    float kr0[4], kr1[4];
    #pragma unroll
    for (int s = 0; s < 4; s++) {
        float vx = (s >= 2) ? 1.0f : -1.0f;
        float vy = (s & 1)  ? 1.0f : -1.0f;
        float c0 = fminf(fmaxf(cy + vx * invtx + 1e-6f, lo), hi);
        float c1 = fminf(fmaxf(cx + vy * invty + 1e-6f, lo), hi);
        int iy = nearest_idx(c0), ix = nearest_idx(c1);
        ky[s] = iy; kx[s] = ix;
        float qc0 = -1.0f + (2.0f * iy + 1.0f) / 64.0f;
        float qc1 = -1.0f + (2.0f * ix + 1.0f) / 64.0f;
        kr0[s] = (cy - qc0) * 64.0f;
        kr1[s] = (cx - qc1) * 64.0f;
    }

    // permuted gather: k' = p*64 + c, reads coalesced in c
    const float* ft = g_featT + (size_t)b * 4096 * CC;
    for (int kp = tid; kp < CK; kp += 128) {
        int p = kp >> 6, c = kp & 63;
        int di = p / 3 - 1, dj = p - (p / 3) * 3 - 1;
        float qacc = 0.f;
        #pragma unroll
        for (int s = 0; s < 4; s++) {
            int y = qy[s] + di, x = qx[s] + dj;
            float v = ((unsigned)y < 64u && (unsigned)x < 64u)
                      ? ft[(size_t)(y * 64 + x) * CC + c] : 0.f;
            qacc += qw[s] * v;
        }
        g_QRYp[(size_t)bq * CKP + kp] = qacc;
        #pragma unroll
        for (int s = 0; s < 4; s++) {
            int y = ky[s] + di, x = kx[s] + dj;
            float v = ((unsigned)y < 64u && (unsigned)x < 64u)
                      ? ft[(size_t)(y * 64 + x) * CC + c] : 0.f;
            g_INPh[((size_t)(bq * 4 + s)) * KINP + kp] = __float2half_rn(v);
        }
    }
    if (tid < 64)        // zero query pad cols 576..639
        g_QRYp[(size_t)bq * CKP + CK + tid] = 0.f;
    if (tid < 4)         // zero attn accumulators (re-zeroed every launch)
        g_attn[bq * 4 + tid] = 0.f;
    {   // cols 576..607: rel(2), scale(2), zeros.
        int s = tid >> 5, cc = tid & 31;
        float v = 0.f;
        if (cc == 0) v = kr0[s];
        else if (cc == 1) v = kr1[s];
        else if (cc == 2) v = s0 * 64.0f;
        else if (cc == 3) v = s1 * 64.0f;
        g_INPh[((size_t)(bq * 4 + s)) * KINP + 576 + cc] = __float2half_rn(v);
    }
}

// ---------------- fp16 mma.sync GEMM (compile-time K, 4-stage) --------------
// EPI 0: half(relu(acc+bias)) -> C.
// EPI 2: z=0 (k): dot((acc+bias)*mul, query) -> atomicAdd g_attn, no store.
//        z=1 (v): half((acc+bias)*mul) -> C.
// EPI 3: fused output projection: relu(acc+bias) @ g_qW2 -> atomicAdd fout.
#define TILEB 8192
#define STAGEB 16384
#define NSTG 4
#define SMEMB (NSTG*STAGEB)         // 65536

__device__ __forceinline__ void cp16(uint32_t dst, const __half* src) {
    asm volatile("cp.async.cg.shared.global [%0], [%1], 16;" :: "r"(dst), "l"(src) : "memory");
}
#define MMA_F16(acc, a0, a1, a2, a3, b0, b1)                                     \
    asm volatile("mma.sync.aligned.m16n8k16.row.col.f32.f16.f16.f32 "            \
        "{%0,%1,%2,%3}, {%4,%5,%6,%7}, {%8,%9}, {%0,%1,%2,%3};"                  \
        : "+f"((acc)[0]), "+f"((acc)[1]), "+f"((acc)[2]), "+f"((acc)[3])         \
        : "r"(a0), "r"(a1), "r"(a2), "r"(a3), "r"(b0), "r"(b1))

template<int EPI, int S>
__global__ __launch_bounds__(256, 2) void mma_gemm(
    const __half* __restrict__ A0, const __half* __restrict__ A1, int lda,
    const __half* __restrict__ B0, const __half* __restrict__ B1,
    __half* __restrict__ C0, __half* __restrict__ C1,
    const float* __restrict__ bias0, const float* __restrict__ bias1,
    const __half* __restrict__ mul, int ldmul, int N, float* fout) {
    extern __shared__ char smem[];
    constexpr int K = 32 * S;
    const int tid = threadIdx.x;
    const int lane = tid & 31, wid = tid >> 5;
    const int g = lane >> 2, tg = lane & 3;
    const int wm = (wid & 3) * 32, wn = (wid >> 2) * 64;
    const int bm = blockIdx.y * 128, bn = blockIdx.x * 128;
    const uint32_t sbase = s2u(smem);

    const __half* A = blockIdx.z ? A1 : A0;
    const __half* B = blockIdx.z ? B1 : B0;
    __half*       C = blockIdx.z ? C1 : C0;
    const float* bias = blockIdx.z ? bias1 : bias0;

    const int ldrow = tid >> 2, ldq = tid & 3;
    const __half* gA0 = A + (size_t)(bm + ldrow) * lda + ldq * 8;
    const __half* gA1 = A + (size_t)(bm + ldrow + 64) * lda + ldq * 8;
    const __half* gB0 = B + (size_t)(bn + ldrow) * K + ldq * 8;
    const __half* gB1 = B + (size_t)(bn + ldrow + 64) * K + ldq * 8;
    const uint32_t sAo = (uint32_t)(ldrow * 64 + ldq * 16);
    const uint32_t sBo = sAo + TILEB;
    const uint32_t sA1o = sAo + 64 * 64;
    const uint32_t sB1o = sBo + 64 * 64;

    float acc[2][8][4];
    #pragma unroll
    for (int mt = 0; mt < 2; mt++)
        #pragma unroll
        for (int nt = 0; nt < 8; nt++)
            #pragma unroll
            for (int j = 0; j < 4; j++) acc[mt][nt][j] = 0.f;

    const uint32_t fa0 = (uint32_t)((wm + g) * 32 + 8 * tg);
    const uint32_t fb0 = (uint32_t)((wn + g) * 32 + 8 * tg);

    #pragma unroll
    for (int p = 0; p < 3; p++) {
        if (p < S) {
            uint32_t st = sbase + p * STAGEB;
            cp16(st + sAo,  gA0 + p * 32);
            cp16(st + sA1o, gA1 + p * 32);
            cp16(st + sBo,  gB0 + p * 32);
            cp16(st + sB1o, gB1 + p * 32);
        }
        asm volatile("cp.async.commit_group;" ::: "memory");
    }

    #pragma unroll
    for (int s = 0; s < S; s++) {
        asm volatile("cp.async.wait_group 2;" ::: "memory");
        __syncthreads();

        if (s + 3 < S) {
            uint32_t st = sbase + ((s + 3) % NSTG) * STAGEB;
            cp16(st + sAo,  gA0 + (s + 3) * 32);
            cp16(st + sA1o, gA1 + (s + 3) * 32);
            cp16(st + sBo,  gB0 + (s + 3) * 32);
            cp16(st + sB1o, gB1 + (s + 3) * 32);
        }
        asm volatile("cp.async.commit_group;" ::: "memory");

        const __half* As = (const __half*)(smem + (s % NSTG) * STAGEB);
        const __half* Bs = As + TILEB / 2;

        uint4 a0[2], a1[2];
        #pragma unroll
        for (int mt = 0; mt < 2; mt++) {
            a0[mt] = *(const uint4*)(As + fa0 + mt * 16 * 32);
            a1[mt] = *(const uint4*)(As + fa0 + mt * 16 * 32 + 8 * 32);
        }
        #pragma unroll
        for (int nt = 0; nt < 8; nt++) {
            uint4 bv = *(const uint4*)(Bs + fb0 + nt * 8 * 32);
            #pragma unroll
            for (int mt = 0; mt < 2; mt++) {
                MMA_F16(acc[mt][nt], a0[mt].x, a1[mt].x, a0[mt].y, a1[mt].y, bv.x, bv.y);
                MMA_F16(acc[mt][nt], a0[mt].z, a1[mt].z, a0[mt].w, a1[mt].w, bv.z, bv.w);
            }
        }
        __syncthreads();
    }

    if (EPI == 0 || (EPI == 2 && blockIdx.z == 1)) {
        #pragma unroll
        for (int mt = 0; mt < 2; mt++) {
            int gm0 = bm + wm + mt * 16 + g;
            #pragma unroll
            for (int nt = 0; nt < 8; nt++) {
                int gn = bn + wn + nt * 8 + 2 * tg;
                float b0 = bias[gn], b1 = bias[gn + 1];
                float v0 = acc[mt][nt][0] + b0;
                float v1 = acc[mt][nt][1] + b1;
                float v2 = acc[mt][nt][2] + b0;
                float v3 = acc[mt][nt][3] + b1;
                if (EPI == 0) {
                    v0 = fmaxf(v0, 0.f); v1 = fmaxf(v1, 0.f);
                    v2 = fmaxf(v2, 0.f); v3 = fmaxf(v3, 0.f);
                } else {
                    float2 m0v = __half22float2(*(const __half2*)(mul + (size_t)gm0 * ldmul + gn));
                    float2 m1v = __half22float2(*(const __half2*)(mul + (size_t)(gm0 + 8) * ldmul + gn));
                    v0 *= m0v.x; v1 *= m0v.y; v2 *= m1v.x; v3 *= m1v.y;
                }
                *(__half2*)(C + (size_t)gm0 * N + gn) = __floats2half2_rn(v0, v1);
                *(__half2*)(C + (size_t)(gm0 + 8) * N + gn) = __floats2half2_rn(v2, v3);
            }
        }
    } else if (EPI == 2) {
        // k-side: fused attention dot, no store
        #pragma unroll
        for (int mt = 0; mt < 2; mt++) {
            int gm0 = bm + wm + mt * 16 + g;
            const float* q0 = g_QRYp + (size_t)(gm0 >> 2) * CKP;
            const float* q1 = g_QRYp + (size_t)((gm0 + 8) >> 2) * CKP;
            float dot0 = 0.f, dot1 = 0.f;
            #pragma unroll
            for (int nt = 0; nt < 8; nt++) {
                int gn = bn + wn + nt * 8 + 2 * tg;
                float b0 = bias[gn], b1 = bias[gn + 1];
                float2 m0v = __half22float2(*(const __half2*)(mul + (size_t)gm0 * ldmul + gn));
                float2 m1v = __half22float2(*(const __half2*)(mul + (size_t)(gm0 + 8) * ldmul + gn));
                float v0 = (acc[mt][nt][0] + b0) * m0v.x;
                float v1 = (acc[mt][nt][1] + b1) * m0v.y;
                float v2 = (acc[mt][nt][2] + b0) * m1v.x;
                float v3 = (acc[mt][nt][3] + b1) * m1v.y;
                float2 qa = *(const float2*)(q0 + gn);
                float2 qb = *(const float2*)(q1 + gn);
                dot0 += v0 * qa.x + v1 * qa.y;
                dot1 += v2 * qb.x + v3 * qb.y;
            }
            dot0 += __shfl_xor_sync(0xffffffffu, dot0, 1);
            dot0 += __shfl_xor_sync(0xffffffffu, dot0, 2);
            dot1 += __shfl_xor_sync(0xffffffffu, dot1, 1);
            dot1 += __shfl_xor_sync(0xffffffffu, dot1, 2);
            if (tg == 0) {
                atomicAdd(&g_attn[gm0], dot0);
                atomicAdd(&g_attn[gm0 + 8], dot1);
            }
        }
    } else {
        // EPI == 3: fused output projection (Hq never materialized)
        float o[2][2][3];
        #pragma unroll
        for (int mt = 0; mt < 2; mt++)
            #pragma unroll
            for (int r = 0; r < 2; r++)
                #pragma unroll
                for (int j = 0; j < 3; j++) o[mt][r][j] = 0.f;
        #pragma unroll
        for (int mt = 0; mt < 2; mt++) {
            #pragma unroll
            for (int nt = 0; nt < 8; nt++) {
                int gn = bn + wn + nt * 8 + 2 * tg;
                float b0 = bias[gn], b1 = bias[gn + 1];
                float v0 = fmaxf(acc[mt][nt][0] + b0, 0.f);
                float v1 = fmaxf(acc[mt][nt][1] + b1, 0.f);
                float v2 = fmaxf(acc[mt][nt][2] + b0, 0.f);
                float v3 = fmaxf(acc[mt][nt][3] + b1, 0.f);
                const float* w0 = g_qW2 + gn * 3;
                #pragma unroll
                for (int j = 0; j < 3; j++) {
                    o[mt][0][j] += v0 * w0[j] + v1 * w0[3 + j];
                    o[mt][1][j] += v2 * w0[j] + v3 * w0[3 + j];
                }
            }
        }
        #pragma unroll
        for (int mt = 0; mt < 2; mt++)
            #pragma unroll
            for (int r = 0; r < 2; r++)
                #pragma unroll
                for (int j = 0; j < 3; j++) {
                    o[mt][r][j] += __shfl_xor_sync(0xffffffffu, o[mt][r][j], 1);
                    o[mt][r][j] += __shfl_xor_sync(0xffffffffu, o[mt][r][j], 2);
                }
        if (tg == 0) {
            #pragma unroll
            for (int mt = 0; mt < 2; mt++) {
                int gm0 = bm + wm + mt * 16 + g;
                #pragma unroll
                for (int j = 0; j < 3; j++) {
                    atomicAdd(&fout[gm0 * 3 + j], o[mt][0][j]);
                    atomicAdd(&fout[(gm0 + 8) * 3 + j], o[mt][1][j]);
                }
            }
        }
    }
}

// ---------------- attnw: inline softmax + weighted PV sum + out init --------
__global__ __launch_bounds__(160) void attnw_kernel(float* __restrict__ out) {
    const int bq = blockIdx.x;
    const int tid = threadIdx.x;
    __shared__ float wsm[4];
    if (tid == 0) {
        float4 a = *(const float4*)&g_attn[bq * 4];
        float m = fmaxf(fmaxf(a.x, a.y), fmaxf(a.z, a.w));
        float e0 = expf(a.x - m), e1 = expf(a.y - m), e2 = expf(a.z - m), e3 = expf(a.w - m);
        float inv = 1.0f / (e0 + e1 + e2 + e3);
        wsm[0] = e0 * inv; wsm[1] = e1 * inv; wsm[2] = e2 * inv; wsm[3] = e3 * inv;
    }
    if (tid >= 4 && tid < 7)        // init out with qb2 (d_out is poisoned)
        out[bq * 3 + (tid - 4)] = g_qb2[tid - 4];
    __syncthreads();
    if (tid < 144) {
        const __half* pv = g_PVh + (size_t)bq * 4 * CKP;
        float x0 = 0.f, x1 = 0.f, x2 = 0.f, x3 = 0.f;
        #pragma unroll
        for (int s = 0; s < 4; s++) {
            float w = wsm[s];
            uint2 u = *(const uint2*)(pv + (size_t)s * CKP + tid * 4);
            float2 f0 = __half22float2(*(__half2*)&u.x);
            float2 f1 = __half22float2(*(__half2*)&u.y);
            x0 += w * f0.x; x1 += w * f0.y;
            x2 += w * f1.x; x3 += w * f1.y;
        }
        __half2* xp = (__half2*)(g_Xh + (size_t)bq * CK);
        xp[tid * 2 + 0] = __floats2half2_rn(x0, x1);
        xp[tid * 2 + 1] = __floats2half2_rn(x2, x3);
    }
}

// ---------------- launch ---------------------------------------------------
extern "C" void kernel_launch(void* const* d_in, const int* in_sizes, int n_in,
                              void* d_out, int out_size) {
    const float* feature = (const float*)d_in[0];
    const float* coord   = (const float*)d_in[1];
    const float* scale   = (const float*)d_in[2];
    const float* kW1 = (const float*)d_in[3];
    const float* kb1 = (const float*)d_in[4];
    const float* kW2 = (const float*)d_in[5];
    const float* kb2 = (const float*)d_in[6];
    const float* vW1 = (const float*)d_in[7];
    const float* vb1 = (const float*)d_in[8];
    const float* vW2 = (const float*)d_in[9];
    const float* vb2 = (const float*)d_in[10];
    const float* qW1 = (const float*)d_in[11];
    const float* qb1 = (const float*)d_in[12];
    const float* qW2 = (const float*)d_in[13];
    const float* qb2 = (const float*)d_in[14];
    float* out = (float*)d_out;

    __half *pINP, *pH, *pPV, *pX, *pW1t, *pkW2t, *pvW2t, *pqW1t;
    float *pb1, *pkb2p, *pvb2p;
    cudaGetSymbolAddress((void**)&pINP,  g_INPh);
    cudaGetSymbolAddress((void**)&pH,    g_Hh);
    cudaGetSymbolAddress((void**)&pPV,   g_PVh);
    cudaGetSymbolAddress((void**)&pX,    g_Xh);
    cudaGetSymbolAddress((void**)&pW1t,  g_W1t);
    cudaGetSymbolAddress((void**)&pb1,   g_b1);
    cudaGetSymbolAddress((void**)&pkW2t, g_kW2t);
    cudaGetSymbolAddress((void**)&pvW2t, g_vW2t);
    cudaGetSymbolAddress((void**)&pkb2p, g_kb2p);
    cudaGetSymbolAddress((void**)&pvb2p, g_vb2p);
    cudaGetSymbolAddress((void**)&pqW1t, g_qW1t);

    cudaFuncSetAttribute(mma_gemm<0, 19>, cudaFuncAttributeMaxDynamicSharedMemorySize, SMEMB);
    cudaFuncSetAttribute(mma_gemm<2, 8>,  cudaFuncAttributeMaxDynamicSharedMemorySize, SMEMB);
    cudaFuncSetAttribute(mma_gemm<3, 18>, cudaFuncAttributeMaxDynamicSharedMemorySize, SMEMB);

    // 0) feature transpose + weight prep
    {
        dim3 tg2(128, 2, BB);
        transpose_feat<<<tg2, 256>>>(feature);
        prep_weights<<<(512 * KINP + 255) / 256, 256>>>(kW1, vW1, kW2, vW2, qW1,
                                                        kb1, vb1, kb2, vb2, qW2, qb2);
    }

    // 1) gather/setup (coalesced; also zeros g_attn + query pad)
    setup_kernel<<<NROW, 128>>>(coord, scale);

    // 2) fused layer-1:  H[:, 0:512] = relu(INP @ W1t^T + b1), K=608, N=512
    {
        dim3 grid(4, NROW4 / 128, 1);
        mma_gemm<0, 19><<<grid, 256, SMEMB>>>(pINP, pINP, KINP, pW1t, pW1t, pH, pH,
                                              pb1, pb1, nullptr, 0, 512, nullptr);
    }

    // 3) layer-2 merged: z=0 k-side (fused dot -> g_attn), z=1 v-side (PV).
    {
        dim3 grid(CKP / 128, NROW4 / 128, 2);
        mma_gemm<2, 8><<<grid, 256, SMEMB>>>(pH, pH + 256, 512, pkW2t, pvW2t,
                                             pPV, pPV, pkb2p, pvb2p,
                                             pINP, KINP, CKP, nullptr);
    }

    // 4) softmax (inline) + weighted PV sum -> X; init out with qb2
    attnw_kernel<<<NROW, 160>>>(out);

    // 5) query MLP + fused output projection: out += relu(X@qW1t^T+qb1)@qW2
    {
        dim3 grid(2, NROW / 128, 1);
        mma_gemm<3, 18><<<grid, 256, SMEMB>>>(pX, pX, CK, pqW1t, pqW1t,
                                              nullptr, nullptr, qb1, qb1,
                                              nullptr, 0, 256, out);
    }
}